// round 1
// baseline (speedup 1.0000x reference)
#include <cuda_runtime.h>
#include <math.h>

#define T 2048
#define HID 2048
#define HQ 32
#define G 2
#define D 64
#define HG 16          // HQ / G
#define C_NUM 127      // compressed windows
#define NB 32          // key blocks
#define TOPK 16
#define WINDOW 512
#define SCALE 0.125f

// ------------------------- scratch (device globals; no allocs) --------------
__device__ float g_q[T * HQ * D];          // 16 MB
__device__ float g_k[T * G * D];
__device__ float g_v[T * G * D];
__device__ float g_gate[T * 3];            // raw pre-sigmoid
__device__ float g_ck[G * C_NUM * D];
__device__ float g_cv[G * C_NUM * D];
__device__ float g_psum[G * T * 128];      // padded C -> 128
__device__ unsigned g_sel[G * T];          // top-k block bitmask
__device__ float g_att[T * HQ * D];        // gated attention output (pre-Wo)

// ------------------------- SGEMM: C[m,n] = sum_k A[m,k] * B[n,k] ------------
// A: MxK row-major, B: NxK row-major. Requires M%128==0, N%128==0, K%8==0.
__global__ __launch_bounds__(256) void sgemm_nt(const float* __restrict__ A,
                                                const float* __restrict__ B,
                                                float* __restrict__ C,
                                                int M, int N, int K) {
    __shared__ float As[8][128];
    __shared__ float Bs[8][128];
    int bm = blockIdx.y * 128, bn = blockIdx.x * 128;
    int tid = threadIdx.x;
    int lr = tid >> 1;              // 0..127: tile row for loads
    int lc = (tid & 1) << 2;        // 0 or 4: k offset for loads
    int tr = (tid >> 4) << 3;       // thread tile row (x8)
    int tc = (tid & 15) << 3;       // thread tile col (x8)
    float acc[8][8];
#pragma unroll
    for (int i = 0; i < 8; i++)
#pragma unroll
        for (int j = 0; j < 8; j++) acc[i][j] = 0.f;

    const float* Aptr = A + (size_t)(bm + lr) * K + lc;
    const float* Bptr = B + (size_t)(bn + lr) * K + lc;

    for (int k0 = 0; k0 < K; k0 += 8) {
        float4 a4 = *(const float4*)(Aptr + k0);
        float4 b4 = *(const float4*)(Bptr + k0);
        As[lc + 0][lr] = a4.x; As[lc + 1][lr] = a4.y;
        As[lc + 2][lr] = a4.z; As[lc + 3][lr] = a4.w;
        Bs[lc + 0][lr] = b4.x; Bs[lc + 1][lr] = b4.y;
        Bs[lc + 2][lr] = b4.z; Bs[lc + 3][lr] = b4.w;
        __syncthreads();
#pragma unroll
        for (int kk = 0; kk < 8; kk++) {
            float4 a0 = *(const float4*)&As[kk][tr];
            float4 a1 = *(const float4*)&As[kk][tr + 4];
            float4 b0 = *(const float4*)&Bs[kk][tc];
            float4 b1 = *(const float4*)&Bs[kk][tc + 4];
            float ra[8] = {a0.x, a0.y, a0.z, a0.w, a1.x, a1.y, a1.z, a1.w};
            float rb[8] = {b0.x, b0.y, b0.z, b0.w, b1.x, b1.y, b1.z, b1.w};
#pragma unroll
            for (int i = 0; i < 8; i++)
#pragma unroll
                for (int j = 0; j < 8; j++) acc[i][j] += ra[i] * rb[j];
        }
        __syncthreads();
    }
#pragma unroll
    for (int i = 0; i < 8; i++) {
        float4 o0 = make_float4(acc[i][0], acc[i][1], acc[i][2], acc[i][3]);
        float4 o1 = make_float4(acc[i][4], acc[i][5], acc[i][6], acc[i][7]);
        float* crow = C + (size_t)(bm + tr + i) * N + bn + tc;
        *(float4*)crow = o0;
        *(float4*)(crow + 4) = o1;
    }
}

// ------------------------- gate = x @ Wgate^T (raw, sigmoid at use) ---------
__global__ void gate_kernel(const float* __restrict__ x,
                            const float* __restrict__ Wg) {
    int t = blockIdx.x;
    int w = threadIdx.x >> 5, lane = threadIdx.x & 31;
    const float* xr = x + (size_t)t * HID;
    const float* wr = Wg + (size_t)w * HID;
    float acc = 0.f;
    for (int i = lane; i < HID; i += 32) acc += xr[i] * wr[i];
#pragma unroll
    for (int off = 16; off; off >>= 1)
        acc += __shfl_xor_sync(0xffffffffu, acc, off);
    if (!lane) g_gate[t * 3 + w] = acc;
}

// ------------------------- RoPE (in place) ----------------------------------
__global__ void rope_kernel(float* x, int nh) {
    int t = blockIdx.x;
    for (int idx = threadIdx.x; idx < nh * 32; idx += blockDim.x) {
        int hh = idx >> 5, d = idx & 31;
        double inv = exp(-(double)d * (log(10000.0) / 32.0));
        double ang = (double)t * inv;
        double sn, cs;
        sincos(ang, &sn, &cs);
        float* p = x + ((size_t)t * nh + hh) * D;
        float x1 = p[d], x2 = p[d + 32];
        p[d]      = (float)((double)x1 * cs - (double)x2 * sn);
        p[d + 32] = (float)((double)x2 * cs + (double)x1 * sn);
    }
}

// ------------------------- compression: ck/cv = window @ W ------------------
__global__ void compress_kernel(const float* __restrict__ Wck,
                                const float* __restrict__ Wcv) {
    int c = blockIdx.x, g = blockIdx.y, which = blockIdx.z;
    const float* src = which ? g_v : g_k;
    const float* W = (which ? Wcv : Wck) + (size_t)g * 2048 * D;
    float* dst = (which ? g_cv : g_ck) + ((size_t)g * C_NUM + c) * D;
    __shared__ float win[32 * 64];
    for (int i = threadIdx.x; i < 2048; i += blockDim.x) {
        int j = i >> 6, dd = i & 63;
        win[i] = src[((size_t)(16 * c + j) * G + g) * D + dd];
    }
    __syncthreads();
    int d = threadIdx.x;  // 0..63
    float acc = 0.f;
#pragma unroll 4
    for (int f = 0; f < 2048; f++) acc += win[f] * W[(size_t)f * D + d];
    dst[d] = acc;
}

// ------------------------- compressed attention + psum ----------------------
__global__ __launch_bounds__(256) void comp_attn_kernel() {
    int t = blockIdx.x, g = blockIdx.y;
    int tid = threadIdx.x;
    int h = tid >> 4, m16 = tid & 15;
    __shared__ float sq[HG * D];
    __shared__ float sbuf[C_NUM][65];   // ck, then cv
    __shared__ float sp[HG][128];

    {   // q for all 16 heads of this group: contiguous 1024 floats
        const float4* src = (const float4*)(g_q + ((size_t)t * HQ + g * HG) * D);
        ((float4*)sq)[tid] = src[tid];
    }
    int nc = (t >= 31) ? ((t - 31) >> 4) + 1 : 0;
    float gate0 = 1.f / (1.f + expf(-g_gate[t * 3 + 0]));
    float* psum_out = g_psum + ((size_t)g * T + t) * 128;
    float* out = g_att + ((size_t)t * HQ + g * HG) * D;
    int d0 = m16 << 2;

    if (nc == 0) {
        *(float4*)(out + h * D + d0) = make_float4(0.f, 0.f, 0.f, 0.f);
        if (tid < 128) psum_out[tid] = 0.f;
        return;
    }
    for (int i = tid; i < nc * D; i += 256) {
        int c = i >> 6, d = i & 63;
        sbuf[c][d] = g_ck[((size_t)g * C_NUM + c) * D + d];
    }
    __syncthreads();

    float sv_[8];
    float mx = -INFINITY;
    const float* qh = sq + h * D;
#pragma unroll
    for (int r = 0; r < 8; r++) {
        int c = r * 16 + m16;
        float acc = -INFINITY;
        if (c < nc) {
            acc = 0.f;
#pragma unroll 8
            for (int d = 0; d < D; d++) acc += qh[d] * sbuf[c][d];
            acc *= SCALE;
        }
        sv_[r] = acc;
        mx = fmaxf(mx, acc);
    }
#pragma unroll
    for (int off = 8; off; off >>= 1)
        mx = fmaxf(mx, __shfl_xor_sync(0xffffffffu, mx, off, 16));
    float l = 0.f;
#pragma unroll
    for (int r = 0; r < 8; r++) { sv_[r] = __expf(sv_[r] - mx); l += sv_[r]; }
#pragma unroll
    for (int off = 8; off; off >>= 1)
        l += __shfl_xor_sync(0xffffffffu, l, off, 16);
    float invl = 1.f / l;
#pragma unroll
    for (int r = 0; r < 8; r++) sp[h][r * 16 + m16] = sv_[r] * invl;
    __syncthreads();

    // psum over heads + reload sbuf with cv
    if (tid < 128) {
        float s = 0.f;
        if (tid < nc) {
#pragma unroll
            for (int hh = 0; hh < HG; hh++) s += sp[hh][tid];
        }
        psum_out[tid] = s;
    }
    for (int i = tid; i < nc * D; i += 256) {
        int c = i >> 6, d = i & 63;
        sbuf[c][d] = g_cv[((size_t)g * C_NUM + c) * D + d];
    }
    __syncthreads();

    float a0 = 0, a1 = 0, a2 = 0, a3 = 0;
    for (int c = 0; c < nc; c++) {
        float p = sp[h][c];
        a0 += p * sbuf[c][d0 + 0];
        a1 += p * sbuf[c][d0 + 1];
        a2 += p * sbuf[c][d0 + 2];
        a3 += p * sbuf[c][d0 + 3];
    }
    out[h * D + d0 + 0] = gate0 * a0;
    out[h * D + d0 + 1] = gate0 * a1;
    out[h * D + d0 + 2] = gate0 * a2;
    out[h * D + d0 + 3] = gate0 * a3;
}

// ------------------------- block score + stable top-k -----------------------
__global__ void select_kernel() {
    int t = blockIdx.x, g = blockIdx.y;
    int b = threadIdx.x;  // 0..31 = block index
    const float* ps = g_psum + ((size_t)g * T + t) * 128;
    float sc = 0.f;
    int clo = 4 * b - 1; if (clo < 0) clo = 0;
    int chi = 4 * b + 3; if (chi > C_NUM - 1) chi = C_NUM - 1;
    for (int c = clo; c <= chi; c++) sc += ps[c];
    int qb = t >> 6;
    bool causal = (b <= qb);
    bool forced = (b < 1) || ((qb - b < 2) && causal);
    float val = causal ? (forced ? INFINITY : sc) : -INFINITY;
    unsigned selbits = 0;
    for (int it = 0; it < TOPK; it++) {
        float rv = val; int ri = b;
#pragma unroll
        for (int off = 16; off; off >>= 1) {
            float ov = __shfl_xor_sync(0xffffffffu, rv, off);
            int oi = __shfl_xor_sync(0xffffffffu, ri, off);
            if (ov > rv || (ov == rv && oi < ri)) { rv = ov; ri = oi; }
        }
        if (rv == -INFINITY) break;   // uniform across warp
        selbits |= (1u << ri);
        if (b == ri) val = -INFINITY;
    }
    if (b == 0) g_sel[(size_t)g * T + t] = selbits;
}

// ------------------------- flash attention (sparse / sliding) ---------------
// mode 0: selected-block sparse; mode 1: sliding window [t-512, t]
__global__ __launch_bounds__(256) void attn_kernel(int mode) {
    int t = blockIdx.x, g = blockIdx.y;
    int tid = threadIdx.x;
    int h = tid >> 4, m16 = tid & 15;
    __shared__ float sq[HG * D];
    __shared__ float sk[D][68];     // [d][s]
    __shared__ float svv[64][64];   // [s][d]
    __shared__ float sp[HG][68];
    {
        const float4* src = (const float4*)(g_q + ((size_t)t * HQ + g * HG) * D);
        ((float4*)sq)[tid] = src[tid];
    }
    int qb = t >> 6;
    unsigned mask = (mode == 0) ? g_sel[(size_t)g * T + t] : 0u;
    int lo = 0, b0 = 0;
    if (mode == 1) {
        lo = t - WINDOW; if (lo < 0) lo = 0;
        b0 = lo >> 6;
    }
    float mi = -INFINITY, li = 0.f;
    float a0 = 0, a1 = 0, a2 = 0, a3 = 0;
    int kk0 = m16 << 2;   // keys owned in score phase
    int d0 = m16 << 2;    // dims owned in AV phase
    const float* qh = sq + h * D;

    for (int b = b0; b <= qb; b++) {
        if (mode == 0 && !((mask >> b) & 1u)) continue;
        int sbase = b << 6;
        int smax = t - sbase; if (smax > 63) smax = 63;
        int smin = lo - sbase; if (smin < 0) smin = 0;
        __syncthreads();
        {   // load K (transposed) and V block
            int s = tid >> 2;
            int dd0 = (tid & 3) << 4;
            const float* kg = g_k + ((size_t)(sbase + s) * G + g) * D + dd0;
            const float* vg = g_v + ((size_t)(sbase + s) * G + g) * D + dd0;
#pragma unroll
            for (int j4 = 0; j4 < 4; j4++) {
                float4 kv = *(const float4*)(kg + j4 * 4);
                sk[dd0 + j4 * 4 + 0][s] = kv.x;
                sk[dd0 + j4 * 4 + 1][s] = kv.y;
                sk[dd0 + j4 * 4 + 2][s] = kv.z;
                sk[dd0 + j4 * 4 + 3][s] = kv.w;
                *(float4*)&svv[s][dd0 + j4 * 4] = *(const float4*)(vg + j4 * 4);
            }
        }
        __syncthreads();
        float s0 = 0, s1 = 0, s2 = 0, s3 = 0;
#pragma unroll 4
        for (int d = 0; d < D; d++) {
            float qv = qh[d];
            float4 kv = *(const float4*)&sk[d][kk0];
            s0 += qv * kv.x; s1 += qv * kv.y; s2 += qv * kv.z; s3 += qv * kv.w;
        }
        s0 = (kk0 + 0 >= smin && kk0 + 0 <= smax) ? s0 * SCALE : -INFINITY;
        s1 = (kk0 + 1 >= smin && kk0 + 1 <= smax) ? s1 * SCALE : -INFINITY;
        s2 = (kk0 + 2 >= smin && kk0 + 2 <= smax) ? s2 * SCALE : -INFINITY;
        s3 = (kk0 + 3 >= smin && kk0 + 3 <= smax) ? s3 * SCALE : -INFINITY;
        float cm = fmaxf(fmaxf(s0, s1), fmaxf(s2, s3));
#pragma unroll
        for (int off = 8; off; off >>= 1)
            cm = fmaxf(cm, __shfl_xor_sync(0xffffffffu, cm, off, 16));
        float mnew = fmaxf(mi, cm);
        float corr = __expf(mi - mnew);
        float p0 = __expf(s0 - mnew), p1 = __expf(s1 - mnew);
        float p2 = __expf(s2 - mnew), p3 = __expf(s3 - mnew);
        float psumv = p0 + p1 + p2 + p3;
#pragma unroll
        for (int off = 8; off; off >>= 1)
            psumv += __shfl_xor_sync(0xffffffffu, psumv, off, 16);
        li = li * corr + psumv;
        mi = mnew;
        sp[h][kk0 + 0] = p0; sp[h][kk0 + 1] = p1;
        sp[h][kk0 + 2] = p2; sp[h][kk0 + 3] = p3;
        a0 *= corr; a1 *= corr; a2 *= corr; a3 *= corr;
        __syncwarp();
        for (int s = smin; s <= smax; s++) {
            float p = sp[h][s];
            float4 vv = *(const float4*)&svv[s][d0];
            a0 += p * vv.x; a1 += p * vv.y; a2 += p * vv.z; a3 += p * vv.w;
        }
    }
    float gv = g_gate[t * 3 + (mode == 0 ? 1 : 2)];
    gv = 1.f / (1.f + expf(-gv));
    float invl = 1.f / li;
    float* out = g_att + ((size_t)t * HQ + g * HG) * D + h * D + d0;
    out[0] += gv * a0 * invl;
    out[1] += gv * a1 * invl;
    out[2] += gv * a2 * invl;
    out[3] += gv * a3 * invl;
}

// ------------------------- launch ------------------------------------------
extern "C" void kernel_launch(void* const* d_in, const int* in_sizes, int n_in,
                              void* d_out, int out_size) {
    const float* x   = (const float*)d_in[0];
    const float* Wq  = (const float*)d_in[1];
    const float* Wk  = (const float*)d_in[2];
    const float* Wv  = (const float*)d_in[3];
    const float* Wo  = (const float*)d_in[4];
    const float* Wg  = (const float*)d_in[5];
    const float* Wck = (const float*)d_in[6];
    const float* Wcv = (const float*)d_in[7];
    float* out = (float*)d_out;

    float *pq, *pk, *pv, *patt;
    cudaGetSymbolAddress((void**)&pq, g_q);
    cudaGetSymbolAddress((void**)&pk, g_k);
    cudaGetSymbolAddress((void**)&pv, g_v);
    cudaGetSymbolAddress((void**)&patt, g_att);

    sgemm_nt<<<dim3((HQ * D) / 128, T / 128), 256>>>(x, Wq, pq, T, HQ * D, HID);
    sgemm_nt<<<dim3((G * D) / 128, T / 128), 256>>>(x, Wk, pk, T, G * D, HID);
    sgemm_nt<<<dim3((G * D) / 128, T / 128), 256>>>(x, Wv, pv, T, G * D, HID);
    gate_kernel<<<T, 96>>>(x, Wg);
    rope_kernel<<<T, 256>>>(pq, HQ);
    rope_kernel<<<T, 64>>>(pk, G);
    compress_kernel<<<dim3(C_NUM, G, 2), 64>>>(Wck, Wcv);
    comp_attn_kernel<<<dim3(T, G), 256>>>();
    select_kernel<<<dim3(T, G), 32>>>();
    attn_kernel<<<dim3(T, G), 256>>>(0);
    attn_kernel<<<dim3(T, G), 256>>>(1);
    sgemm_nt<<<dim3(HID / 128, T / 128), 256>>>(patt, Wo, out, T, HID, HID);
}

// round 3
// speedup vs baseline: 1.1395x; 1.1395x over previous
#include <cuda_runtime.h>
#include <cuda_bf16.h>
#include <math.h>
#include <stdint.h>

#define T 2048
#define HID 2048
#define HQ 32
#define G 2
#define D 64
#define HG 16          // HQ / G
#define C_NUM 127      // compressed windows
#define NB 32          // key blocks
#define TOPK 16
#define WINDOW 512
#define SCALE 0.125f

// ------------------------- scratch (device globals; no allocs) --------------
__device__ float g_q[T * HQ * D];
__device__ float g_k[T * G * D];
__device__ float g_v[T * G * D];
__device__ float g_gate[T * 3];
__device__ float g_ck[G * C_NUM * D];
__device__ float g_cv[G * C_NUM * D];
__device__ float g_psum[G * T * 128];
__device__ unsigned g_sel[G * T];
__device__ float g_att[T * HQ * D];

// bf16 split buffers for tensor-core GEMMs
__device__ __align__(16) __nv_bfloat16 g_xh[T * HID];
__device__ __align__(16) __nv_bfloat16 g_xl[T * HID];
__device__ __align__(16) __nv_bfloat16 g_wqh[HQ * D * HID];
__device__ __align__(16) __nv_bfloat16 g_wql[HQ * D * HID];
__device__ __align__(16) __nv_bfloat16 g_woh[HID * HID];
__device__ __align__(16) __nv_bfloat16 g_wol[HID * HID];
__device__ __align__(16) __nv_bfloat16 g_ath[T * HID];
__device__ __align__(16) __nv_bfloat16 g_atl[T * HID];

// ------------------------- fp32 -> bf16 hi/lo split --------------------------
__global__ void split_kernel(const float* __restrict__ src,
                             __nv_bfloat16* __restrict__ hi,
                             __nv_bfloat16* __restrict__ lo, int n) {
    int i = (blockIdx.x * blockDim.x + threadIdx.x) * 4;
    if (i >= n) return;
    float4 v = *(const float4*)(src + i);
    __nv_bfloat16 h0 = __float2bfloat16(v.x);
    __nv_bfloat16 h1 = __float2bfloat16(v.y);
    __nv_bfloat16 h2 = __float2bfloat16(v.z);
    __nv_bfloat16 h3 = __float2bfloat16(v.w);
    __nv_bfloat16 l0 = __float2bfloat16(v.x - __bfloat162float(h0));
    __nv_bfloat16 l1 = __float2bfloat16(v.y - __bfloat162float(h1));
    __nv_bfloat16 l2 = __float2bfloat16(v.z - __bfloat162float(h2));
    __nv_bfloat16 l3 = __float2bfloat16(v.w - __bfloat162float(h3));
    ((__nv_bfloat162*)(hi + i))[0] = __halves2bfloat162(h0, h1);
    ((__nv_bfloat162*)(hi + i))[1] = __halves2bfloat162(h2, h3);
    ((__nv_bfloat162*)(lo + i))[0] = __halves2bfloat162(l0, l1);
    ((__nv_bfloat162*)(lo + i))[1] = __halves2bfloat162(l2, l3);
}

// ------------------------- bf16x3 tensor-core GEMM ---------------------------
// C[m,n] = sum_k A[m,k]*B[n,k], fp32-equivalent via bf16 hi/lo split.
// M,N multiples of 128; K multiple of 32.
#define SMS 40  // smem row stride (bf16 elems), conflict-free for ldmatrix

#define LDSM4(r0, r1, r2, r3, addr)                                       \
    asm volatile("ldmatrix.sync.aligned.m8n8.x4.shared.b16 "              \
                 "{%0,%1,%2,%3}, [%4];"                                   \
                 : "=r"(r0), "=r"(r1), "=r"(r2), "=r"(r3) : "r"(addr))

#define MMA_BF16(dd, aa, bb)                                              \
    asm volatile("mma.sync.aligned.m16n8k16.row.col.f32.bf16.bf16.f32 "   \
                 "{%0,%1,%2,%3},{%4,%5,%6,%7},{%8,%9},{%0,%1,%2,%3};"     \
                 : "+f"(dd[0]), "+f"(dd[1]), "+f"(dd[2]), "+f"(dd[3])     \
                 : "r"(aa[0]), "r"(aa[1]), "r"(aa[2]), "r"(aa[3]),        \
                   "r"(bb[0]), "r"(bb[1]))

__global__ __launch_bounds__(256) void gemm_bf16x3(
    const __nv_bfloat16* __restrict__ Ah, const __nv_bfloat16* __restrict__ Al,
    const __nv_bfloat16* __restrict__ Bh, const __nv_bfloat16* __restrict__ Bl,
    float* __restrict__ C, int M, int N, int K) {
    __shared__ __nv_bfloat16 sAh[128 * SMS], sAl[128 * SMS];
    __shared__ __nv_bfloat16 sBh[128 * SMS], sBl[128 * SMS];

    int tid = threadIdx.x;
    int bm = blockIdx.y * 128, bn = blockIdx.x * 128;
    int lrow = tid >> 1, lcol = (tid & 1) << 4;   // 128 rows x 32 cols coverage
    int wid = tid >> 5, lane = tid & 31;
    int wm = wid & 1, wn = wid >> 1;
    int m0 = wm * 64, n0 = wn * 32;
    int g8 = lane >> 2, tig = lane & 3;

    const __nv_bfloat16* pAh = Ah + (size_t)(bm + lrow) * K + lcol;
    const __nv_bfloat16* pAl = Al + (size_t)(bm + lrow) * K + lcol;
    const __nv_bfloat16* pBh = Bh + (size_t)(bn + lrow) * K + lcol;
    const __nv_bfloat16* pBl = Bl + (size_t)(bn + lrow) * K + lcol;

    float acc[4][4][4];
#pragma unroll
    for (int i = 0; i < 4; i++)
#pragma unroll
        for (int j = 0; j < 4; j++)
#pragma unroll
            for (int r = 0; r < 4; r++) acc[i][j][r] = 0.f;

    // ldmatrix source element offsets (per lane)
    int aoff = (m0 + (lane & 7) + ((lane >> 3) & 1) * 8) * SMS + (lane >> 4) * 8;
    int boff = (n0 + (lane & 7) + (lane >> 4) * 8) * SMS + ((lane >> 3) & 1) * 8;
    unsigned int uAh = (unsigned int)__cvta_generic_to_shared(sAh);
    unsigned int uAl = (unsigned int)__cvta_generic_to_shared(sAl);
    unsigned int uBh = (unsigned int)__cvta_generic_to_shared(sBh);
    unsigned int uBl = (unsigned int)__cvta_generic_to_shared(sBl);

    uint4 vah0, vah1, val0, val1, vbh0, vbh1, vbl0, vbl1;
    vah0 = *(const uint4*)(pAh);     vah1 = *(const uint4*)(pAh + 8);
    val0 = *(const uint4*)(pAl);     val1 = *(const uint4*)(pAl + 8);
    vbh0 = *(const uint4*)(pBh);     vbh1 = *(const uint4*)(pBh + 8);
    vbl0 = *(const uint4*)(pBl);     vbl1 = *(const uint4*)(pBl + 8);

    int sidx = lrow * SMS + lcol;
    for (int k0 = 0; k0 < K; k0 += 32) {
        *(uint4*)&sAh[sidx] = vah0; *(uint4*)&sAh[sidx + 8] = vah1;
        *(uint4*)&sAl[sidx] = val0; *(uint4*)&sAl[sidx + 8] = val1;
        *(uint4*)&sBh[sidx] = vbh0; *(uint4*)&sBh[sidx + 8] = vbh1;
        *(uint4*)&sBl[sidx] = vbl0; *(uint4*)&sBl[sidx + 8] = vbl1;
        __syncthreads();
        if (k0 + 32 < K) {
            int kn = k0 + 32;
            vah0 = *(const uint4*)(pAh + kn); vah1 = *(const uint4*)(pAh + kn + 8);
            val0 = *(const uint4*)(pAl + kn); val1 = *(const uint4*)(pAl + kn + 8);
            vbh0 = *(const uint4*)(pBh + kn); vbh1 = *(const uint4*)(pBh + kn + 8);
            vbl0 = *(const uint4*)(pBl + kn); vbl1 = *(const uint4*)(pBl + kn + 8);
        }
#pragma unroll
        for (int kk = 0; kk < 32; kk += 16) {
            unsigned int ah[4][4], al[4][4], bh[4][2], bl[4][2];
#pragma unroll
            for (int i = 0; i < 4; i++) {
                unsigned int ad = (unsigned int)((aoff + i * 16 * SMS + kk) * 2);
                LDSM4(ah[i][0], ah[i][1], ah[i][2], ah[i][3], uAh + ad);
                LDSM4(al[i][0], al[i][1], al[i][2], al[i][3], uAl + ad);
            }
#pragma unroll
            for (int j2 = 0; j2 < 2; j2++) {
                unsigned int bd = (unsigned int)((boff + j2 * 16 * SMS + kk) * 2);
                LDSM4(bh[2 * j2][0], bh[2 * j2][1], bh[2 * j2 + 1][0],
                      bh[2 * j2 + 1][1], uBh + bd);
                LDSM4(bl[2 * j2][0], bl[2 * j2][1], bl[2 * j2 + 1][0],
                      bl[2 * j2 + 1][1], uBl + bd);
            }
#pragma unroll
            for (int i = 0; i < 4; i++)
#pragma unroll
                for (int j = 0; j < 4; j++) {
                    MMA_BF16(acc[i][j], ah[i], bh[j]);
                    MMA_BF16(acc[i][j], ah[i], bl[j]);
                    MMA_BF16(acc[i][j], al[i], bh[j]);
                }
        }
        __syncthreads();
    }
    // epilogue
#pragma unroll
    for (int i = 0; i < 4; i++) {
        int r0 = bm + m0 + i * 16 + g8;
#pragma unroll
        for (int j = 0; j < 4; j++) {
            int col = bn + n0 + j * 8 + tig * 2;
            *(float2*)(C + (size_t)r0 * N + col) =
                make_float2(acc[i][j][0], acc[i][j][1]);
            *(float2*)(C + (size_t)(r0 + 8) * N + col) =
                make_float2(acc[i][j][2], acc[i][j][3]);
        }
    }
}

// ------------------------- fp32 SGEMM (small N: k/v projections) ------------
__global__ __launch_bounds__(256) void sgemm_nt(const float* __restrict__ A,
                                                const float* __restrict__ B,
                                                float* __restrict__ C,
                                                int M, int N, int K) {
    __shared__ float As[8][128];
    __shared__ float Bs[8][128];
    int bm = blockIdx.y * 128, bn = blockIdx.x * 128;
    int tid = threadIdx.x;
    int lr = tid >> 1;
    int lc = (tid & 1) << 2;
    int tr = (tid >> 4) << 3;
    int tc = (tid & 15) << 3;
    float acc[8][8];
#pragma unroll
    for (int i = 0; i < 8; i++)
#pragma unroll
        for (int j = 0; j < 8; j++) acc[i][j] = 0.f;

    const float* Aptr = A + (size_t)(bm + lr) * K + lc;
    const float* Bptr = B + (size_t)(bn + lr) * K + lc;

    for (int k0 = 0; k0 < K; k0 += 8) {
        float4 a4 = *(const float4*)(Aptr + k0);
        float4 b4 = *(const float4*)(Bptr + k0);
        As[lc + 0][lr] = a4.x; As[lc + 1][lr] = a4.y;
        As[lc + 2][lr] = a4.z; As[lc + 3][lr] = a4.w;
        Bs[lc + 0][lr] = b4.x; Bs[lc + 1][lr] = b4.y;
        Bs[lc + 2][lr] = b4.z; Bs[lc + 3][lr] = b4.w;
        __syncthreads();
#pragma unroll
        for (int kk = 0; kk < 8; kk++) {
            float4 a0 = *(const float4*)&As[kk][tr];
            float4 a1 = *(const float4*)&As[kk][tr + 4];
            float4 b0 = *(const float4*)&Bs[kk][tc];
            float4 b1 = *(const float4*)&Bs[kk][tc + 4];
            float ra[8] = {a0.x, a0.y, a0.z, a0.w, a1.x, a1.y, a1.z, a1.w};
            float rb[8] = {b0.x, b0.y, b0.z, b0.w, b1.x, b1.y, b1.z, b1.w};
#pragma unroll
            for (int i = 0; i < 8; i++)
#pragma unroll
                for (int j = 0; j < 8; j++) acc[i][j] += ra[i] * rb[j];
        }
        __syncthreads();
    }
#pragma unroll
    for (int i = 0; i < 8; i++) {
        float4 o0 = make_float4(acc[i][0], acc[i][1], acc[i][2], acc[i][3]);
        float4 o1 = make_float4(acc[i][4], acc[i][5], acc[i][6], acc[i][7]);
        float* crow = C + (size_t)(bm + tr + i) * N + bn + tc;
        *(float4*)crow = o0;
        *(float4*)(crow + 4) = o1;
    }
}

// ------------------------- gate = x @ Wgate^T --------------------------------
__global__ void gate_kernel(const float* __restrict__ x,
                            const float* __restrict__ Wg) {
    int t = blockIdx.x;
    int w = threadIdx.x >> 5, lane = threadIdx.x & 31;
    const float* xr = x + (size_t)t * HID;
    const float* wr = Wg + (size_t)w * HID;
    float acc = 0.f;
    for (int i = lane; i < HID; i += 32) acc += xr[i] * wr[i];
#pragma unroll
    for (int off = 16; off; off >>= 1)
        acc += __shfl_xor_sync(0xffffffffu, acc, off);
    if (!lane) g_gate[t * 3 + w] = acc;
}

// ------------------------- RoPE ----------------------------------------------
__global__ void rope_kernel(float* x, int nh) {
    int t = blockIdx.x;
    for (int idx = threadIdx.x; idx < nh * 32; idx += blockDim.x) {
        int hh = idx >> 5, d = idx & 31;
        double inv = exp(-(double)d * (log(10000.0) / 32.0));
        double ang = (double)t * inv;
        double sn, cs;
        sincos(ang, &sn, &cs);
        float* p = x + ((size_t)t * nh + hh) * D;
        float x1 = p[d], x2 = p[d + 32];
        p[d]      = (float)((double)x1 * cs - (double)x2 * sn);
        p[d + 32] = (float)((double)x2 * cs + (double)x1 * sn);
    }
}

// ------------------------- compression ---------------------------------------
__global__ void compress_kernel(const float* __restrict__ Wck,
                                const float* __restrict__ Wcv) {
    int c = blockIdx.x, g = blockIdx.y, which = blockIdx.z;
    const float* src = which ? g_v : g_k;
    const float* W = (which ? Wcv : Wck) + (size_t)g * 2048 * D;
    float* dst = (which ? g_cv : g_ck) + ((size_t)g * C_NUM + c) * D;
    __shared__ float win[32 * 64];
    for (int i = threadIdx.x; i < 2048; i += blockDim.x) {
        int j = i >> 6, dd = i & 63;
        win[i] = src[((size_t)(16 * c + j) * G + g) * D + dd];
    }
    __syncthreads();
    int d = threadIdx.x;
    float acc = 0.f;
#pragma unroll 4
    for (int f = 0; f < 2048; f++) acc += win[f] * W[(size_t)f * D + d];
    dst[d] = acc;
}

// ------------------------- compressed attention + psum -----------------------
__global__ __launch_bounds__(256) void comp_attn_kernel() {
    int t = blockIdx.x, g = blockIdx.y;
    int tid = threadIdx.x;
    int h = tid >> 4, m16 = tid & 15;
    __shared__ float sq[HG * D];
    __shared__ float sbuf[C_NUM][65];
    __shared__ float sp[HG][128];

    {
        const float4* src = (const float4*)(g_q + ((size_t)t * HQ + g * HG) * D);
        ((float4*)sq)[tid] = src[tid];
    }
    int nc = (t >= 31) ? ((t - 31) >> 4) + 1 : 0;
    float gate0 = 1.f / (1.f + expf(-g_gate[t * 3 + 0]));
    float* psum_out = g_psum + ((size_t)g * T + t) * 128;
    float* out = g_att + ((size_t)t * HQ + g * HG) * D;
    int d0 = m16 << 2;

    if (nc == 0) {
        *(float4*)(out + h * D + d0) = make_float4(0.f, 0.f, 0.f, 0.f);
        if (tid < 128) psum_out[tid] = 0.f;
        return;
    }
    for (int i = tid; i < nc * D; i += 256) {
        int c = i >> 6, d = i & 63;
        sbuf[c][d] = g_ck[((size_t)g * C_NUM + c) * D + d];
    }
    __syncthreads();

    float sv_[8];
    float mx = -INFINITY;
    const float* qh = sq + h * D;
#pragma unroll
    for (int r = 0; r < 8; r++) {
        int c = r * 16 + m16;
        float acc = -INFINITY;
        if (c < nc) {
            acc = 0.f;
#pragma unroll 8
            for (int d = 0; d < D; d++) acc += qh[d] * sbuf[c][d];
            acc *= SCALE;
        }
        sv_[r] = acc;
        mx = fmaxf(mx, acc);
    }
#pragma unroll
    for (int off = 8; off; off >>= 1)
        mx = fmaxf(mx, __shfl_xor_sync(0xffffffffu, mx, off, 16));
    float l = 0.f;
#pragma unroll
    for (int r = 0; r < 8; r++) { sv_[r] = __expf(sv_[r] - mx); l += sv_[r]; }
#pragma unroll
    for (int off = 8; off; off >>= 1)
        l += __shfl_xor_sync(0xffffffffu, l, off, 16);
    float invl = 1.f / l;
#pragma unroll
    for (int r = 0; r < 8; r++) sp[h][r * 16 + m16] = sv_[r] * invl;
    __syncthreads();

    if (tid < 128) {
        float s = 0.f;
        if (tid < nc) {
#pragma unroll
            for (int hh = 0; hh < HG; hh++) s += sp[hh][tid];
        }
        psum_out[tid] = s;
    }
    for (int i = tid; i < nc * D; i += 256) {
        int c = i >> 6, d = i & 63;
        sbuf[c][d] = g_cv[((size_t)g * C_NUM + c) * D + d];
    }
    __syncthreads();

    float a0 = 0, a1 = 0, a2 = 0, a3 = 0;
    for (int c = 0; c < nc; c++) {
        float p = sp[h][c];
        a0 += p * sbuf[c][d0 + 0];
        a1 += p * sbuf[c][d0 + 1];
        a2 += p * sbuf[c][d0 + 2];
        a3 += p * sbuf[c][d0 + 3];
    }
    out[h * D + d0 + 0] = gate0 * a0;
    out[h * D + d0 + 1] = gate0 * a1;
    out[h * D + d0 + 2] = gate0 * a2;
    out[h * D + d0 + 3] = gate0 * a3;
}

// ------------------------- block score + stable top-k ------------------------
__global__ void select_kernel() {
    int t = blockIdx.x, g = blockIdx.y;
    int b = threadIdx.x;
    const float* ps = g_psum + ((size_t)g * T + t) * 128;
    float sc = 0.f;
    int clo = 4 * b - 1; if (clo < 0) clo = 0;
    int chi = 4 * b + 3; if (chi > C_NUM - 1) chi = C_NUM - 1;
    for (int c = clo; c <= chi; c++) sc += ps[c];
    int qb = t >> 6;
    bool causal = (b <= qb);
    bool forced = (b < 1) || ((qb - b < 2) && causal);
    float val = causal ? (forced ? INFINITY : sc) : -INFINITY;
    unsigned selbits = 0;
    for (int it = 0; it < TOPK; it++) {
        float rv = val; int ri = b;
#pragma unroll
        for (int off = 16; off; off >>= 1) {
            float ov = __shfl_xor_sync(0xffffffffu, rv, off);
            int oi = __shfl_xor_sync(0xffffffffu, ri, off);
            if (ov > rv || (ov == rv && oi < ri)) { rv = ov; ri = oi; }
        }
        if (rv == -INFINITY) break;
        selbits |= (1u << ri);
        if (b == ri) val = -INFINITY;
    }
    if (b == 0) g_sel[(size_t)g * T + t] = selbits;
}

// ------------------------- flash attention (sparse / sliding) ----------------
__global__ __launch_bounds__(256) void attn_kernel(int mode) {
    int t = blockIdx.x, g = blockIdx.y;
    int tid = threadIdx.x;
    int h = tid >> 4, m16 = tid & 15;
    __shared__ float sq[HG * D];
    __shared__ float sk[D][68];
    __shared__ float svv[64][64];
    __shared__ float sp[HG][68];
    {
        const float4* src = (const float4*)(g_q + ((size_t)t * HQ + g * HG) * D);
        ((float4*)sq)[tid] = src[tid];
    }
    int qb = t >> 6;
    unsigned mask = (mode == 0) ? g_sel[(size_t)g * T + t] : 0u;
    int lo = 0, b0 = 0;
    if (mode == 1) {
        lo = t - WINDOW; if (lo < 0) lo = 0;
        b0 = lo >> 6;
    }
    float mi = -INFINITY, li = 0.f;
    float a0 = 0, a1 = 0, a2 = 0, a3 = 0;
    int kk0 = m16 << 2;
    int d0 = m16 << 2;
    const float* qh = sq + h * D;

    for (int b = b0; b <= qb; b++) {
        if (mode == 0 && !((mask >> b) & 1u)) continue;
        int sbase = b << 6;
        int smax = t - sbase; if (smax > 63) smax = 63;
        int smin = lo - sbase; if (smin < 0) smin = 0;
        __syncthreads();
        {
            int s = tid >> 2;
            int dd0 = (tid & 3) << 4;
            const float* kg = g_k + ((size_t)(sbase + s) * G + g) * D + dd0;
            const float* vg = g_v + ((size_t)(sbase + s) * G + g) * D + dd0;
#pragma unroll
            for (int j4 = 0; j4 < 4; j4++) {
                float4 kv = *(const float4*)(kg + j4 * 4);
                sk[dd0 + j4 * 4 + 0][s] = kv.x;
                sk[dd0 + j4 * 4 + 1][s] = kv.y;
                sk[dd0 + j4 * 4 + 2][s] = kv.z;
                sk[dd0 + j4 * 4 + 3][s] = kv.w;
                *(float4*)&svv[s][dd0 + j4 * 4] = *(const float4*)(vg + j4 * 4);
            }
        }
        __syncthreads();
        float s0 = 0, s1 = 0, s2 = 0, s3 = 0;
#pragma unroll 4
        for (int d = 0; d < D; d++) {
            float qv = qh[d];
            float4 kv = *(const float4*)&sk[d][kk0];
            s0 += qv * kv.x; s1 += qv * kv.y; s2 += qv * kv.z; s3 += qv * kv.w;
        }
        s0 = (kk0 + 0 >= smin && kk0 + 0 <= smax) ? s0 * SCALE : -INFINITY;
        s1 = (kk0 + 1 >= smin && kk0 + 1 <= smax) ? s1 * SCALE : -INFINITY;
        s2 = (kk0 + 2 >= smin && kk0 + 2 <= smax) ? s2 * SCALE : -INFINITY;
        s3 = (kk0 + 3 >= smin && kk0 + 3 <= smax) ? s3 * SCALE : -INFINITY;
        float cm = fmaxf(fmaxf(s0, s1), fmaxf(s2, s3));
#pragma unroll
        for (int off = 8; off; off >>= 1)
            cm = fmaxf(cm, __shfl_xor_sync(0xffffffffu, cm, off, 16));
        float mnew = fmaxf(mi, cm);
        float corr = __expf(mi - mnew);
        float p0 = __expf(s0 - mnew), p1 = __expf(s1 - mnew);
        float p2 = __expf(s2 - mnew), p3 = __expf(s3 - mnew);
        float psumv = p0 + p1 + p2 + p3;
#pragma unroll
        for (int off = 8; off; off >>= 1)
            psumv += __shfl_xor_sync(0xffffffffu, psumv, off, 16);
        li = li * corr + psumv;
        mi = mnew;
        sp[h][kk0 + 0] = p0; sp[h][kk0 + 1] = p1;
        sp[h][kk0 + 2] = p2; sp[h][kk0 + 3] = p3;
        a0 *= corr; a1 *= corr; a2 *= corr; a3 *= corr;
        __syncwarp();
        for (int s = smin; s <= smax; s++) {
            float p = sp[h][s];
            float4 vv = *(const float4*)&svv[s][d0];
            a0 += p * vv.x; a1 += p * vv.y; a2 += p * vv.z; a3 += p * vv.w;
        }
    }
    float gv = g_gate[t * 3 + (mode == 0 ? 1 : 2)];
    gv = 1.f / (1.f + expf(-gv));
    float invl = 1.f / li;
    float* out = g_att + ((size_t)t * HQ + g * HG) * D + h * D + d0;
    out[0] += gv * a0 * invl;
    out[1] += gv * a1 * invl;
    out[2] += gv * a2 * invl;
    out[3] += gv * a3 * invl;
}

// ------------------------- launch --------------------------------------------
extern "C" void kernel_launch(void* const* d_in, const int* in_sizes, int n_in,
                              void* d_out, int out_size) {
    const float* x   = (const float*)d_in[0];
    const float* Wq  = (const float*)d_in[1];
    const float* Wk  = (const float*)d_in[2];
    const float* Wv  = (const float*)d_in[3];
    const float* Wo  = (const float*)d_in[4];
    const float* Wg  = (const float*)d_in[5];
    const float* Wck = (const float*)d_in[6];
    const float* Wcv = (const float*)d_in[7];
    float* out = (float*)d_out;

    float *pq, *pk, *pv, *patt;
    cudaGetSymbolAddress((void**)&pq, g_q);
    cudaGetSymbolAddress((void**)&pk, g_k);
    cudaGetSymbolAddress((void**)&pv, g_v);
    cudaGetSymbolAddress((void**)&patt, g_att);
    __nv_bfloat16 *xh, *xl, *wqh, *wql, *woh, *wol, *ath, *atl;
    cudaGetSymbolAddress((void**)&xh, g_xh);
    cudaGetSymbolAddress((void**)&xl, g_xl);
    cudaGetSymbolAddress((void**)&wqh, g_wqh);
    cudaGetSymbolAddress((void**)&wql, g_wql);
    cudaGetSymbolAddress((void**)&woh, g_woh);
    cudaGetSymbolAddress((void**)&wol, g_wol);
    cudaGetSymbolAddress((void**)&ath, g_ath);
    cudaGetSymbolAddress((void**)&atl, g_atl);

    const int NELT = T * HID;
    split_kernel<<<NELT / 1024, 256>>>(x, xh, xl, NELT);
    split_kernel<<<NELT / 1024, 256>>>(Wq, wqh, wql, NELT);
    split_kernel<<<NELT / 1024, 256>>>(Wo, woh, wol, NELT);

    gemm_bf16x3<<<dim3((HQ * D) / 128, T / 128), 256>>>(xh, xl, wqh, wql, pq,
                                                        T, HQ * D, HID);
    sgemm_nt<<<dim3((G * D) / 128, T / 128), 256>>>(x, Wk, pk, T, G * D, HID);
    sgemm_nt<<<dim3((G * D) / 128, T / 128), 256>>>(x, Wv, pv, T, G * D, HID);
    gate_kernel<<<T, 96>>>(x, Wg);
    rope_kernel<<<T, 256>>>(pq, HQ);
    rope_kernel<<<T, 64>>>(pk, G);
    compress_kernel<<<dim3(C_NUM, G, 2), 64>>>(Wck, Wcv);
    comp_attn_kernel<<<dim3(T, G), 256>>>();
    select_kernel<<<dim3(T, G), 32>>>();
    attn_kernel<<<dim3(T, G), 256>>>(0);
    attn_kernel<<<dim3(T, G), 256>>>(1);

    split_kernel<<<NELT / 1024, 256>>>(patt, ath, atl, NELT);
    gemm_bf16x3<<<dim3(HID / 128, T / 128), 256>>>(ath, atl, woh, wol, out,
                                                   T, HID, HID);
}

// round 4
// speedup vs baseline: 1.8534x; 1.6265x over previous
#include <cuda_runtime.h>
#include <cuda_bf16.h>
#include <math.h>
#include <stdint.h>

#define T 2048
#define HID 2048
#define HQ 32
#define G 2
#define D 64
#define HG 16          // HQ / G
#define C_NUM 127      // compressed windows
#define TOPK 16
#define WINDOW 512
#define SCALE 0.125f

// ------------------------- scratch (device globals; no allocs) --------------
__device__ float g_q[T * HQ * D];
__device__ float g_k[T * G * D];
__device__ float g_v[T * G * D];
__device__ float g_gate[T * 3];
__device__ float g_ck[G * C_NUM * D];
__device__ float g_cv[G * C_NUM * D];
__device__ float g_psum[G * T * 128];
__device__ unsigned g_sel[G * T];
__device__ float g_att[T * HQ * D];
__device__ float g_cos[T * 32];
__device__ float g_sin[T * 32];

// bf16 split buffers for tensor-core GEMMs
__device__ __align__(16) __nv_bfloat16 g_xh[T * HID];
__device__ __align__(16) __nv_bfloat16 g_xl[T * HID];
__device__ __align__(16) __nv_bfloat16 g_wqh[HQ * D * HID];
__device__ __align__(16) __nv_bfloat16 g_wql[HQ * D * HID];
__device__ __align__(16) __nv_bfloat16 g_wkh[G * D * HID];
__device__ __align__(16) __nv_bfloat16 g_wkl[G * D * HID];
__device__ __align__(16) __nv_bfloat16 g_wvh[G * D * HID];
__device__ __align__(16) __nv_bfloat16 g_wvl[G * D * HID];
__device__ __align__(16) __nv_bfloat16 g_woh[HID * HID];
__device__ __align__(16) __nv_bfloat16 g_wol[HID * HID];
__device__ __align__(16) __nv_bfloat16 g_ath[T * HID];
__device__ __align__(16) __nv_bfloat16 g_atl[T * HID];

// ------------------------- fp32 -> bf16 hi/lo split --------------------------
__global__ void split_kernel(const float* __restrict__ src,
                             __nv_bfloat16* __restrict__ hi,
                             __nv_bfloat16* __restrict__ lo, int n) {
    int i = (blockIdx.x * blockDim.x + threadIdx.x) * 4;
    if (i >= n) return;
    float4 v = *(const float4*)(src + i);
    __nv_bfloat16 h0 = __float2bfloat16(v.x);
    __nv_bfloat16 h1 = __float2bfloat16(v.y);
    __nv_bfloat16 h2 = __float2bfloat16(v.z);
    __nv_bfloat16 h3 = __float2bfloat16(v.w);
    __nv_bfloat16 l0 = __float2bfloat16(v.x - __bfloat162float(h0));
    __nv_bfloat16 l1 = __float2bfloat16(v.y - __bfloat162float(h1));
    __nv_bfloat16 l2 = __float2bfloat16(v.z - __bfloat162float(h2));
    __nv_bfloat16 l3 = __float2bfloat16(v.w - __bfloat162float(h3));
    ((__nv_bfloat162*)(hi + i))[0] = __halves2bfloat162(h0, h1);
    ((__nv_bfloat162*)(hi + i))[1] = __halves2bfloat162(h2, h3);
    ((__nv_bfloat162*)(lo + i))[0] = __halves2bfloat162(l0, l1);
    ((__nv_bfloat162*)(lo + i))[1] = __halves2bfloat162(l2, l3);
}

// ------------------------- bf16x3 tensor-core GEMM ---------------------------
// C[m,n] = sum_k A[m,k]*B[n,k]. If blockIdx.z==1, uses (Bh2,Bl2,C2).
#define SMS 40  // smem row stride (bf16 elems)

#define LDSM4(r0, r1, r2, r3, addr)                                       \
    asm volatile("ldmatrix.sync.aligned.m8n8.x4.shared.b16 "              \
                 "{%0,%1,%2,%3}, [%4];"                                   \
                 : "=r"(r0), "=r"(r1), "=r"(r2), "=r"(r3) : "r"(addr))

#define MMA_BF16(dd, aa, bb)                                              \
    asm volatile("mma.sync.aligned.m16n8k16.row.col.f32.bf16.bf16.f32 "   \
                 "{%0,%1,%2,%3},{%4,%5,%6,%7},{%8,%9},{%0,%1,%2,%3};"     \
                 : "+f"(dd[0]), "+f"(dd[1]), "+f"(dd[2]), "+f"(dd[3])     \
                 : "r"(aa[0]), "r"(aa[1]), "r"(aa[2]), "r"(aa[3]),        \
                   "r"(bb[0]), "r"(bb[1]))

__global__ __launch_bounds__(256) void gemm_bf16x3(
    const __nv_bfloat16* __restrict__ Ah, const __nv_bfloat16* __restrict__ Al,
    const __nv_bfloat16* __restrict__ Bh, const __nv_bfloat16* __restrict__ Bl,
    float* __restrict__ C,
    const __nv_bfloat16* __restrict__ Bh2, const __nv_bfloat16* __restrict__ Bl2,
    float* __restrict__ C2, int M, int N, int K) {
    __shared__ __nv_bfloat16 sAh[128 * SMS], sAl[128 * SMS];
    __shared__ __nv_bfloat16 sBh[128 * SMS], sBl[128 * SMS];

    if (blockIdx.z) { Bh = Bh2; Bl = Bl2; C = C2; }

    int tid = threadIdx.x;
    int bm = blockIdx.y * 128, bn = blockIdx.x * 128;
    int lrow = tid >> 1, lcol = (tid & 1) << 4;
    int wid = tid >> 5, lane = tid & 31;
    int wm = wid & 1, wn = wid >> 1;
    int m0 = wm * 64, n0 = wn * 32;
    int g8 = lane >> 2, tig = lane & 3;

    const __nv_bfloat16* pAh = Ah + (size_t)(bm + lrow) * K + lcol;
    const __nv_bfloat16* pAl = Al + (size_t)(bm + lrow) * K + lcol;
    const __nv_bfloat16* pBh = Bh + (size_t)(bn + lrow) * K + lcol;
    const __nv_bfloat16* pBl = Bl + (size_t)(bn + lrow) * K + lcol;

    float acc[4][4][4];
#pragma unroll
    for (int i = 0; i < 4; i++)
#pragma unroll
        for (int j = 0; j < 4; j++)
#pragma unroll
            for (int r = 0; r < 4; r++) acc[i][j][r] = 0.f;

    int aoff = (m0 + (lane & 7) + ((lane >> 3) & 1) * 8) * SMS + (lane >> 4) * 8;
    int boff = (n0 + (lane & 7) + (lane >> 4) * 8) * SMS + ((lane >> 3) & 1) * 8;
    unsigned int uAh = (unsigned int)__cvta_generic_to_shared(sAh);
    unsigned int uAl = (unsigned int)__cvta_generic_to_shared(sAl);
    unsigned int uBh = (unsigned int)__cvta_generic_to_shared(sBh);
    unsigned int uBl = (unsigned int)__cvta_generic_to_shared(sBl);

    uint4 vah0, vah1, val0, val1, vbh0, vbh1, vbl0, vbl1;
    vah0 = *(const uint4*)(pAh);     vah1 = *(const uint4*)(pAh + 8);
    val0 = *(const uint4*)(pAl);     val1 = *(const uint4*)(pAl + 8);
    vbh0 = *(const uint4*)(pBh);     vbh1 = *(const uint4*)(pBh + 8);
    vbl0 = *(const uint4*)(pBl);     vbl1 = *(const uint4*)(pBl + 8);

    int sidx = lrow * SMS + lcol;
    for (int k0 = 0; k0 < K; k0 += 32) {
        *(uint4*)&sAh[sidx] = vah0; *(uint4*)&sAh[sidx + 8] = vah1;
        *(uint4*)&sAl[sidx] = val0; *(uint4*)&sAl[sidx + 8] = val1;
        *(uint4*)&sBh[sidx] = vbh0; *(uint4*)&sBh[sidx + 8] = vbh1;
        *(uint4*)&sBl[sidx] = vbl0; *(uint4*)&sBl[sidx + 8] = vbl1;
        __syncthreads();
        if (k0 + 32 < K) {
            int kn = k0 + 32;
            vah0 = *(const uint4*)(pAh + kn); vah1 = *(const uint4*)(pAh + kn + 8);
            val0 = *(const uint4*)(pAl + kn); val1 = *(const uint4*)(pAl + kn + 8);
            vbh0 = *(const uint4*)(pBh + kn); vbh1 = *(const uint4*)(pBh + kn + 8);
            vbl0 = *(const uint4*)(pBl + kn); vbl1 = *(const uint4*)(pBl + kn + 8);
        }
#pragma unroll
        for (int kk = 0; kk < 32; kk += 16) {
            unsigned int ah[4][4], al[4][4], bh[4][2], bl[4][2];
#pragma unroll
            for (int i = 0; i < 4; i++) {
                unsigned int ad = (unsigned int)((aoff + i * 16 * SMS + kk) * 2);
                LDSM4(ah[i][0], ah[i][1], ah[i][2], ah[i][3], uAh + ad);
                LDSM4(al[i][0], al[i][1], al[i][2], al[i][3], uAl + ad);
            }
#pragma unroll
            for (int j2 = 0; j2 < 2; j2++) {
                unsigned int bd = (unsigned int)((boff + j2 * 16 * SMS + kk) * 2);
                LDSM4(bh[2 * j2][0], bh[2 * j2][1], bh[2 * j2 + 1][0],
                      bh[2 * j2 + 1][1], uBh + bd);
                LDSM4(bl[2 * j2][0], bl[2 * j2][1], bl[2 * j2 + 1][0],
                      bl[2 * j2 + 1][1], uBl + bd);
            }
#pragma unroll
            for (int i = 0; i < 4; i++)
#pragma unroll
                for (int j = 0; j < 4; j++) {
                    MMA_BF16(acc[i][j], ah[i], bh[j]);
                    MMA_BF16(acc[i][j], ah[i], bl[j]);
                    MMA_BF16(acc[i][j], al[i], bh[j]);
                }
        }
        __syncthreads();
    }
#pragma unroll
    for (int i = 0; i < 4; i++) {
        int r0 = bm + m0 + i * 16 + g8;
#pragma unroll
        for (int j = 0; j < 4; j++) {
            int col = bn + n0 + j * 8 + tig * 2;
            *(float2*)(C + (size_t)r0 * N + col) =
                make_float2(acc[i][j][0], acc[i][j][1]);
            *(float2*)(C + (size_t)(r0 + 8) * N + col) =
                make_float2(acc[i][j][2], acc[i][j][3]);
        }
    }
}

// ------------------------- gate = x @ Wgate^T --------------------------------
__global__ void gate_kernel(const float* __restrict__ x,
                            const float* __restrict__ Wg) {
    int t = blockIdx.x;
    int w = threadIdx.x >> 5, lane = threadIdx.x & 31;
    const float* xr = x + (size_t)t * HID;
    const float* wr = Wg + (size_t)w * HID;
    float acc = 0.f;
    for (int i = lane; i < HID; i += 32) acc += xr[i] * wr[i];
#pragma unroll
    for (int off = 16; off; off >>= 1)
        acc += __shfl_xor_sync(0xffffffffu, acc, off);
    if (!lane) g_gate[t * 3 + w] = acc;
}

// ------------------------- RoPE: table + apply --------------------------------
__global__ void rope_table_kernel() {
    int t = blockIdx.x, d = threadIdx.x;
    double inv = exp(-(double)d * (log(10000.0) / 32.0));
    double sn, cs;
    sincos((double)t * inv, &sn, &cs);
    g_cos[t * 32 + d] = (float)cs;
    g_sin[t * 32 + d] = (float)sn;
}

__global__ void rope_apply_kernel(float* x, int nh) {
    int t = blockIdx.x;
    for (int idx = threadIdx.x; idx < nh * 32; idx += blockDim.x) {
        int hh = idx >> 5, d = idx & 31;
        float cs = g_cos[t * 32 + d], sn = g_sin[t * 32 + d];
        float* p = x + ((size_t)t * nh + hh) * D;
        float x1 = p[d], x2 = p[d + 32];
        p[d]      = x1 * cs - x2 * sn;
        p[d + 32] = x2 * cs + x1 * sn;
    }
}

// ------------------------- compression ---------------------------------------
__global__ void compress_kernel(const float* __restrict__ Wck,
                                const float* __restrict__ Wcv) {
    int c = blockIdx.x, g = blockIdx.y, which = blockIdx.z;
    const float* src = which ? g_v : g_k;
    const float* W = (which ? Wcv : Wck) + (size_t)g * 2048 * D;
    float* dst = (which ? g_cv : g_ck) + ((size_t)g * C_NUM + c) * D;
    __shared__ float win[32 * 64];
    for (int i = threadIdx.x; i < 2048; i += blockDim.x) {
        int j = i >> 6, dd = i & 63;
        win[i] = src[((size_t)(16 * c + j) * G + g) * D + dd];
    }
    __syncthreads();
    int d = threadIdx.x;
    float acc = 0.f;
#pragma unroll 4
    for (int f = 0; f < 2048; f++) acc += win[f] * W[(size_t)f * D + d];
    dst[d] = acc;
}

// ------------------------- compressed attention + psum -----------------------
__global__ __launch_bounds__(256) void comp_attn_kernel() {
    int t = blockIdx.x, g = blockIdx.y;
    int tid = threadIdx.x;
    int h = tid >> 4, m16 = tid & 15;
    __shared__ float sq[HG * D];
    __shared__ float sbuf[C_NUM][65];
    __shared__ float sp[HG][128];

    {
        const float4* src = (const float4*)(g_q + ((size_t)t * HQ + g * HG) * D);
        ((float4*)sq)[tid] = src[tid];
    }
    int nc = (t >= 31) ? ((t - 31) >> 4) + 1 : 0;
    float gate0 = 1.f / (1.f + expf(-g_gate[t * 3 + 0]));
    float* psum_out = g_psum + ((size_t)g * T + t) * 128;
    float* out = g_att + ((size_t)t * HQ + g * HG) * D;
    int d0 = m16 << 2;

    if (nc == 0) {
        *(float4*)(out + h * D + d0) = make_float4(0.f, 0.f, 0.f, 0.f);
        if (tid < 128) psum_out[tid] = 0.f;
        return;
    }
    for (int i = tid; i < nc * D; i += 256) {
        int c = i >> 6, d = i & 63;
        sbuf[c][d] = g_ck[((size_t)g * C_NUM + c) * D + d];
    }
    __syncthreads();

    float sv_[8];
    float mx = -INFINITY;
    const float* qh = sq + h * D;
#pragma unroll
    for (int r = 0; r < 8; r++) {
        int c = r * 16 + m16;
        float acc = -INFINITY;
        if (c < nc) {
            acc = 0.f;
#pragma unroll 8
            for (int d = 0; d < D; d++) acc += qh[d] * sbuf[c][d];
            acc *= SCALE;
        }
        sv_[r] = acc;
        mx = fmaxf(mx, acc);
    }
#pragma unroll
    for (int off = 8; off; off >>= 1)
        mx = fmaxf(mx, __shfl_xor_sync(0xffffffffu, mx, off, 16));
    float l = 0.f;
#pragma unroll
    for (int r = 0; r < 8; r++) { sv_[r] = __expf(sv_[r] - mx); l += sv_[r]; }
#pragma unroll
    for (int off = 8; off; off >>= 1)
        l += __shfl_xor_sync(0xffffffffu, l, off, 16);
    float invl = 1.f / l;
#pragma unroll
    for (int r = 0; r < 8; r++) sp[h][r * 16 + m16] = sv_[r] * invl;
    __syncthreads();

    if (tid < 128) {
        float s = 0.f;
        if (tid < nc) {
#pragma unroll
            for (int hh = 0; hh < HG; hh++) s += sp[hh][tid];
        }
        psum_out[tid] = s;
    }
    for (int i = tid; i < nc * D; i += 256) {
        int c = i >> 6, d = i & 63;
        sbuf[c][d] = g_cv[((size_t)g * C_NUM + c) * D + d];
    }
    __syncthreads();

    float a0 = 0, a1 = 0, a2 = 0, a3 = 0;
    for (int c = 0; c < nc; c++) {
        float p = sp[h][c];
        a0 += p * sbuf[c][d0 + 0];
        a1 += p * sbuf[c][d0 + 1];
        a2 += p * sbuf[c][d0 + 2];
        a3 += p * sbuf[c][d0 + 3];
    }
    out[h * D + d0 + 0] = gate0 * a0;
    out[h * D + d0 + 1] = gate0 * a1;
    out[h * D + d0 + 2] = gate0 * a2;
    out[h * D + d0 + 3] = gate0 * a3;
}

// ------------------------- block score + stable top-k ------------------------
__global__ void select_kernel() {
    int t = blockIdx.x, g = blockIdx.y;
    int b = threadIdx.x;
    const float* ps = g_psum + ((size_t)g * T + t) * 128;
    float sc = 0.f;
    int clo = 4 * b - 1; if (clo < 0) clo = 0;
    int chi = 4 * b + 3; if (chi > C_NUM - 1) chi = C_NUM - 1;
    for (int c = clo; c <= chi; c++) sc += ps[c];
    int qb = t >> 6;
    bool causal = (b <= qb);
    bool forced = (b < 1) || ((qb - b < 2) && causal);
    float val = causal ? (forced ? INFINITY : sc) : -INFINITY;
    unsigned selbits = 0;
    for (int it = 0; it < TOPK; it++) {
        float rv = val; int ri = b;
#pragma unroll
        for (int off = 16; off; off >>= 1) {
            float ov = __shfl_xor_sync(0xffffffffu, rv, off);
            int oi = __shfl_xor_sync(0xffffffffu, ri, off);
            if (ov > rv || (ov == rv && oi < ri)) { rv = ov; ri = oi; }
        }
        if (rv == -INFINITY) break;
        selbits |= (1u << ri);
        if (b == ri) val = -INFINITY;
    }
    if (b == 0) g_sel[(size_t)g * T + t] = selbits;
}

// ------------------------- merged flash attention (sparse + sliding) ---------
__device__ __forceinline__ void attn_load_regs(int sbase, int g, int s, int dg,
                                               float4* kr, float4* vr) {
    const float4* kg =
        (const float4*)(g_k + ((size_t)(sbase + s) * G + g) * D + dg);
    const float4* vg =
        (const float4*)(g_v + ((size_t)(sbase + s) * G + g) * D + dg);
#pragma unroll
    for (int j = 0; j < 4; j++) { kr[j] = kg[j]; vr[j] = vg[j]; }
}

__global__ __launch_bounds__(256, 2) void attn_merged_kernel() {
    int t = blockIdx.x, g = blockIdx.y;
    int tid = threadIdx.x;
    int lane = tid & 31;
    int h = ((tid >> 5) << 1) + (lane >> 4);   // head 0..15
    int l16 = lane & 15;
    int k0 = l16 << 2;                          // key quad / d quad

    __shared__ float skT[D][68];
    __shared__ float sv[64][68];
    __shared__ float sq[HG][64];
    __shared__ float sp1[HG][64];
    __shared__ float sp2[HG][64];

    ((float4*)sq)[tid] =
        ((const float4*)(g_q + ((size_t)t * HQ + g * HG) * D))[tid];

    int qb = t >> 6;
    unsigned msel = g_sel[(size_t)g * T + t];
    int lo = t - WINDOW; if (lo < 0) lo = 0;
    int bw0 = lo >> 6;
    unsigned mwin = ((2u << qb) - 1) & ~((1u << bw0) - 1);
    unsigned mall = msel | mwin;

    int s = tid >> 2, dg = (tid & 3) << 4;

    float mi1 = -INFINITY, li1 = 0.f, mi2 = -INFINITY, li2 = 0.f;
    float4 acc1 = make_float4(0, 0, 0, 0), acc2 = make_float4(0, 0, 0, 0);

    float4 kr[4], vr[4];
    unsigned rem = mall;
    {
        int b = __ffs(rem) - 1;
        attn_load_regs(b << 6, g, s, dg, kr, vr);
    }
    while (rem) {
        int b = __ffs(rem) - 1; rem &= rem - 1;
        int sbase = b << 6;
        __syncthreads();   // prior smem reads done (also covers sq on iter 1)
#pragma unroll
        for (int j = 0; j < 4; j++) {
            int d = dg + 4 * j;
            skT[d + 0][s] = kr[j].x; skT[d + 1][s] = kr[j].y;
            skT[d + 2][s] = kr[j].z; skT[d + 3][s] = kr[j].w;
            *(float4*)&sv[s][d] = vr[j];
        }
        __syncthreads();
        if (rem) {
            int bn = __ffs(rem) - 1;
            attn_load_regs(bn << 6, g, s, dg, kr, vr);
        }
        // shared QK scores
        float s0 = 0, s1 = 0, s2 = 0, s3 = 0;
        const float* qh = sq[h];
#pragma unroll
        for (int d = 0; d < D; d++) {
            float4 kv = *(const float4*)&skT[d][k0];
            float qd = qh[d];
            s0 += qd * kv.x; s1 += qd * kv.y; s2 += qd * kv.z; s3 += qd * kv.w;
        }
        s0 *= SCALE; s1 *= SCALE; s2 *= SCALE; s3 *= SCALE;
        int smax = t - sbase; if (smax > 63) smax = 63;
        bool act1 = (msel >> b) & 1u;
        bool act2 = (mwin >> b) & 1u;
        int smin2 = lo - sbase; if (smin2 < 0) smin2 = 0;

        if (act1) {
            float v0 = (k0 + 0 <= smax) ? s0 : -INFINITY;
            float v1 = (k0 + 1 <= smax) ? s1 : -INFINITY;
            float v2 = (k0 + 2 <= smax) ? s2 : -INFINITY;
            float v3 = (k0 + 3 <= smax) ? s3 : -INFINITY;
            float cm = fmaxf(fmaxf(v0, v1), fmaxf(v2, v3));
#pragma unroll
            for (int off = 8; off; off >>= 1)
                cm = fmaxf(cm, __shfl_xor_sync(0xffffffffu, cm, off, 16));
            float mnew = fmaxf(mi1, cm);
            float corr = __expf(mi1 - mnew);
            float p0 = __expf(v0 - mnew), p1 = __expf(v1 - mnew);
            float p2 = __expf(v2 - mnew), p3 = __expf(v3 - mnew);
            float ps = p0 + p1 + p2 + p3;
#pragma unroll
            for (int off = 8; off; off >>= 1)
                ps += __shfl_xor_sync(0xffffffffu, ps, off, 16);
            li1 = li1 * corr + ps;
            mi1 = mnew;
            sp1[h][k0 + 0] = p0; sp1[h][k0 + 1] = p1;
            sp1[h][k0 + 2] = p2; sp1[h][k0 + 3] = p3;
            acc1.x *= corr; acc1.y *= corr; acc1.z *= corr; acc1.w *= corr;
        }
        if (act2) {
            float v0 = (k0 + 0 >= smin2 && k0 + 0 <= smax) ? s0 : -INFINITY;
            float v1 = (k0 + 1 >= smin2 && k0 + 1 <= smax) ? s1 : -INFINITY;
            float v2 = (k0 + 2 >= smin2 && k0 + 2 <= smax) ? s2 : -INFINITY;
            float v3 = (k0 + 3 >= smin2 && k0 + 3 <= smax) ? s3 : -INFINITY;
            float cm = fmaxf(fmaxf(v0, v1), fmaxf(v2, v3));
#pragma unroll
            for (int off = 8; off; off >>= 1)
                cm = fmaxf(cm, __shfl_xor_sync(0xffffffffu, cm, off, 16));
            float mnew = fmaxf(mi2, cm);
            float corr = __expf(mi2 - mnew);
            float p0 = __expf(v0 - mnew), p1 = __expf(v1 - mnew);
            float p2 = __expf(v2 - mnew), p3 = __expf(v3 - mnew);
            float ps = p0 + p1 + p2 + p3;
#pragma unroll
            for (int off = 8; off; off >>= 1)
                ps += __shfl_xor_sync(0xffffffffu, ps, off, 16);
            li2 = li2 * corr + ps;
            mi2 = mnew;
            sp2[h][k0 + 0] = p0; sp2[h][k0 + 1] = p1;
            sp2[h][k0 + 2] = p2; sp2[h][k0 + 3] = p3;
            acc2.x *= corr; acc2.y *= corr; acc2.z *= corr; acc2.w *= corr;
        }
        __syncwarp();
        if (act1) {
            for (int ss = 0; ss <= smax; ss++) {
                float p = sp1[h][ss];
                float4 vv = *(const float4*)&sv[ss][k0];
                acc1.x += p * vv.x; acc1.y += p * vv.y;
                acc1.z += p * vv.z; acc1.w += p * vv.w;
            }
        }
        if (act2) {
            for (int ss = smin2; ss <= smax; ss++) {
                float p = sp2[h][ss];
                float4 vv = *(const float4*)&sv[ss][k0];
                acc2.x += p * vv.x; acc2.y += p * vv.y;
                acc2.z += p * vv.z; acc2.w += p * vv.w;
            }
        }
    }
    float g1 = 1.f / (1.f + expf(-g_gate[t * 3 + 1]));
    float g2 = 1.f / (1.f + expf(-g_gate[t * 3 + 2]));
    float w1 = g1 / li1, w2 = g2 / li2;
    float* out = g_att + ((size_t)t * HQ + g * HG + h) * D + k0;
    float4 o = *(float4*)out;
    o.x += w1 * acc1.x + w2 * acc2.x;
    o.y += w1 * acc1.y + w2 * acc2.y;
    o.z += w1 * acc1.z + w2 * acc2.z;
    o.w += w1 * acc1.w + w2 * acc2.w;
    *(float4*)out = o;
}

// ------------------------- launch --------------------------------------------
extern "C" void kernel_launch(void* const* d_in, const int* in_sizes, int n_in,
                              void* d_out, int out_size) {
    const float* x   = (const float*)d_in[0];
    const float* Wq  = (const float*)d_in[1];
    const float* Wk  = (const float*)d_in[2];
    const float* Wv  = (const float*)d_in[3];
    const float* Wo  = (const float*)d_in[4];
    const float* Wg  = (const float*)d_in[5];
    const float* Wck = (const float*)d_in[6];
    const float* Wcv = (const float*)d_in[7];
    float* out = (float*)d_out;

    float *pq, *pk, *pv, *patt;
    cudaGetSymbolAddress((void**)&pq, g_q);
    cudaGetSymbolAddress((void**)&pk, g_k);
    cudaGetSymbolAddress((void**)&pv, g_v);
    cudaGetSymbolAddress((void**)&patt, g_att);
    __nv_bfloat16 *xh, *xl, *wqh, *wql, *wkh, *wkl, *wvh, *wvl, *woh, *wol,
        *ath, *atl;
    cudaGetSymbolAddress((void**)&xh, g_xh);
    cudaGetSymbolAddress((void**)&xl, g_xl);
    cudaGetSymbolAddress((void**)&wqh, g_wqh);
    cudaGetSymbolAddress((void**)&wql, g_wql);
    cudaGetSymbolAddress((void**)&wkh, g_wkh);
    cudaGetSymbolAddress((void**)&wkl, g_wkl);
    cudaGetSymbolAddress((void**)&wvh, g_wvh);
    cudaGetSymbolAddress((void**)&wvl, g_wvl);
    cudaGetSymbolAddress((void**)&woh, g_woh);
    cudaGetSymbolAddress((void**)&wol, g_wol);
    cudaGetSymbolAddress((void**)&ath, g_ath);
    cudaGetSymbolAddress((void**)&atl, g_atl);

    const int NELT = T * HID;
    const int NKV = G * D * HID;
    split_kernel<<<NELT / 1024, 256>>>(x, xh, xl, NELT);
    split_kernel<<<NELT / 1024, 256>>>(Wq, wqh, wql, NELT);
    split_kernel<<<NKV / 1024, 256>>>(Wk, wkh, wkl, NKV);
    split_kernel<<<NKV / 1024, 256>>>(Wv, wvh, wvl, NKV);
    split_kernel<<<NELT / 1024, 256>>>(Wo, woh, wol, NELT);
    rope_table_kernel<<<T, 32>>>();

    gemm_bf16x3<<<dim3((HQ * D) / 128, T / 128, 1), 256>>>(
        xh, xl, wqh, wql, pq, wqh, wql, pq, T, HQ * D, HID);
    gemm_bf16x3<<<dim3(1, T / 128, 2), 256>>>(
        xh, xl, wkh, wkl, pk, wvh, wvl, pv, T, G * D, HID);
    gate_kernel<<<T, 96>>>(x, Wg);
    rope_apply_kernel<<<T, 256>>>(pq, HQ);
    rope_apply_kernel<<<T, 64>>>(pk, G);
    compress_kernel<<<dim3(C_NUM, G, 2), 64>>>(Wck, Wcv);
    comp_attn_kernel<<<dim3(T, G), 256>>>();
    select_kernel<<<dim3(T, G), 32>>>();
    attn_merged_kernel<<<dim3(T, G), 256>>>();

    split_kernel<<<NELT / 1024, 256>>>(patt, ath, atl, NELT);
    gemm_bf16x3<<<dim3(HID / 128, T / 128, 1), 256>>>(
        ath, atl, woh, wol, out, woh, wol, out, T, HID, HID);
}

// round 5
// speedup vs baseline: 2.7270x; 1.4714x over previous
#include <cuda_runtime.h>
#include <cuda_bf16.h>
#include <math.h>
#include <stdint.h>

#define T 2048
#define HID 2048
#define HQ 32
#define G 2
#define D 64
#define HG 16          // HQ / G
#define C_NUM 127      // compressed windows
#define TOPK 16
#define WINDOW 512
#define SCALE 0.125f

// ------------------------- scratch (device globals; no allocs) --------------
__device__ float g_q[T * HQ * D];
__device__ float g_k[T * G * D];
__device__ float g_v[T * G * D];
__device__ float g_gate[T * 3];
__device__ float g_ck[G * C_NUM * D];
__device__ float g_cv[G * C_NUM * D];
__device__ float g_psum[G * T * 128];
__device__ unsigned g_sel[G * T];
__device__ float g_att[T * HQ * D];
__device__ float g_cos[T * 32];
__device__ float g_sin[T * 32];

// bf16 split buffers
__device__ __align__(16) __nv_bfloat16 g_xh[T * HID];
__device__ __align__(16) __nv_bfloat16 g_xl[T * HID];
__device__ __align__(16) __nv_bfloat16 g_wqh[HQ * D * HID];
__device__ __align__(16) __nv_bfloat16 g_wql[HQ * D * HID];
__device__ __align__(16) __nv_bfloat16 g_wkh[G * D * HID];
__device__ __align__(16) __nv_bfloat16 g_wkl[G * D * HID];
__device__ __align__(16) __nv_bfloat16 g_wvh[G * D * HID];
__device__ __align__(16) __nv_bfloat16 g_wvl[G * D * HID];
__device__ __align__(16) __nv_bfloat16 g_woh[HID * HID];
__device__ __align__(16) __nv_bfloat16 g_wol[HID * HID];
__device__ __align__(16) __nv_bfloat16 g_ath[T * HID];
__device__ __align__(16) __nv_bfloat16 g_atl[T * HID];
// attention K/V bf16 hi/lo (K row-major, V transposed [g][d][t])
__device__ __align__(16) __nv_bfloat16 g_kh[T * G * D];
__device__ __align__(16) __nv_bfloat16 g_kl[T * G * D];
__device__ __align__(16) __nv_bfloat16 g_vth[G * D * T];
__device__ __align__(16) __nv_bfloat16 g_vtl[G * D * T];

// ------------------------- helpers ------------------------------------------
__device__ __forceinline__ void split2(float x, float y, unsigned& h,
                                       unsigned& l) {
    __nv_bfloat162 hh = __floats2bfloat162_rn(x, y);
    float hx = __bfloat162float(__low2bfloat16(hh));
    float hy = __bfloat162float(__high2bfloat16(hh));
    __nv_bfloat162 ll = __floats2bfloat162_rn(x - hx, y - hy);
    h = *reinterpret_cast<unsigned*>(&hh);
    l = *reinterpret_cast<unsigned*>(&ll);
}

// ------------------------- fp32 -> bf16 hi/lo split --------------------------
__global__ void split_kernel(const float* __restrict__ src,
                             __nv_bfloat16* __restrict__ hi,
                             __nv_bfloat16* __restrict__ lo, int n) {
    int i = (blockIdx.x * blockDim.x + threadIdx.x) * 4;
    if (i >= n) return;
    float4 v = *(const float4*)(src + i);
    unsigned h0, l0, h1, l1;
    split2(v.x, v.y, h0, l0);
    split2(v.z, v.w, h1, l1);
    ((unsigned*)(hi + i))[0] = h0;
    ((unsigned*)(hi + i))[1] = h1;
    ((unsigned*)(lo + i))[0] = l0;
    ((unsigned*)(lo + i))[1] = l1;
}

// K split + V transpose/split (after RoPE)
__global__ void kvsplit_kernel() {
    int i = blockIdx.x * blockDim.x + threadIdx.x;  // over T*G*D
    float kv = g_k[i];
    __nv_bfloat16 h = __float2bfloat16(kv);
    g_kh[i] = h;
    g_kl[i] = __float2bfloat16(kv - __bfloat162float(h));
    int t = i >> 7, gd = i & 127;
    float vv = g_v[i];
    __nv_bfloat16 vh = __float2bfloat16(vv);
    int o = gd * T + t;
    g_vth[o] = vh;
    g_vtl[o] = __float2bfloat16(vv - __bfloat162float(vh));
}

// ------------------------- bf16x3 tensor-core GEMM ---------------------------
#define SMS 40

#define LDSM4(r0, r1, r2, r3, addr)                                       \
    asm volatile("ldmatrix.sync.aligned.m8n8.x4.shared.b16 "              \
                 "{%0,%1,%2,%3}, [%4];"                                   \
                 : "=r"(r0), "=r"(r1), "=r"(r2), "=r"(r3) : "r"(addr))

#define MMA_BF16(dd, aa, bb)                                              \
    asm volatile("mma.sync.aligned.m16n8k16.row.col.f32.bf16.bf16.f32 "   \
                 "{%0,%1,%2,%3},{%4,%5,%6,%7},{%8,%9},{%0,%1,%2,%3};"     \
                 : "+f"(dd[0]), "+f"(dd[1]), "+f"(dd[2]), "+f"(dd[3])     \
                 : "r"(aa[0]), "r"(aa[1]), "r"(aa[2]), "r"(aa[3]),        \
                   "r"(bb[0]), "r"(bb[1]))

__global__ __launch_bounds__(256) void gemm_bf16x3(
    const __nv_bfloat16* __restrict__ Ah, const __nv_bfloat16* __restrict__ Al,
    const __nv_bfloat16* __restrict__ Bh, const __nv_bfloat16* __restrict__ Bl,
    float* __restrict__ C,
    const __nv_bfloat16* __restrict__ Bh2, const __nv_bfloat16* __restrict__ Bl2,
    float* __restrict__ C2, int M, int N, int K) {
    __shared__ __nv_bfloat16 sAh[128 * SMS], sAl[128 * SMS];
    __shared__ __nv_bfloat16 sBh[128 * SMS], sBl[128 * SMS];

    if (blockIdx.z) { Bh = Bh2; Bl = Bl2; C = C2; }

    int tid = threadIdx.x;
    int bm = blockIdx.y * 128, bn = blockIdx.x * 128;
    int lrow = tid >> 1, lcol = (tid & 1) << 4;
    int wid = tid >> 5, lane = tid & 31;
    int wm = wid & 1, wn = wid >> 1;
    int m0 = wm * 64, n0 = wn * 32;
    int g8 = lane >> 2, tig = lane & 3;

    const __nv_bfloat16* pAh = Ah + (size_t)(bm + lrow) * K + lcol;
    const __nv_bfloat16* pAl = Al + (size_t)(bm + lrow) * K + lcol;
    const __nv_bfloat16* pBh = Bh + (size_t)(bn + lrow) * K + lcol;
    const __nv_bfloat16* pBl = Bl + (size_t)(bn + lrow) * K + lcol;

    float acc[4][4][4];
#pragma unroll
    for (int i = 0; i < 4; i++)
#pragma unroll
        for (int j = 0; j < 4; j++)
#pragma unroll
            for (int r = 0; r < 4; r++) acc[i][j][r] = 0.f;

    int aoff = (m0 + (lane & 7) + ((lane >> 3) & 1) * 8) * SMS + (lane >> 4) * 8;
    int boff = (n0 + (lane & 7) + (lane >> 4) * 8) * SMS + ((lane >> 3) & 1) * 8;
    unsigned int uAh = (unsigned int)__cvta_generic_to_shared(sAh);
    unsigned int uAl = (unsigned int)__cvta_generic_to_shared(sAl);
    unsigned int uBh = (unsigned int)__cvta_generic_to_shared(sBh);
    unsigned int uBl = (unsigned int)__cvta_generic_to_shared(sBl);

    uint4 vah0, vah1, val0, val1, vbh0, vbh1, vbl0, vbl1;
    vah0 = *(const uint4*)(pAh);     vah1 = *(const uint4*)(pAh + 8);
    val0 = *(const uint4*)(pAl);     val1 = *(const uint4*)(pAl + 8);
    vbh0 = *(const uint4*)(pBh);     vbh1 = *(const uint4*)(pBh + 8);
    vbl0 = *(const uint4*)(pBl);     vbl1 = *(const uint4*)(pBl + 8);

    int sidx = lrow * SMS + lcol;
    for (int k0 = 0; k0 < K; k0 += 32) {
        *(uint4*)&sAh[sidx] = vah0; *(uint4*)&sAh[sidx + 8] = vah1;
        *(uint4*)&sAl[sidx] = val0; *(uint4*)&sAl[sidx + 8] = val1;
        *(uint4*)&sBh[sidx] = vbh0; *(uint4*)&sBh[sidx + 8] = vbh1;
        *(uint4*)&sBl[sidx] = vbl0; *(uint4*)&sBl[sidx + 8] = vbl1;
        __syncthreads();
        if (k0 + 32 < K) {
            int kn = k0 + 32;
            vah0 = *(const uint4*)(pAh + kn); vah1 = *(const uint4*)(pAh + kn + 8);
            val0 = *(const uint4*)(pAl + kn); val1 = *(const uint4*)(pAl + kn + 8);
            vbh0 = *(const uint4*)(pBh + kn); vbh1 = *(const uint4*)(pBh + kn + 8);
            vbl0 = *(const uint4*)(pBl + kn); vbl1 = *(const uint4*)(pBl + kn + 8);
        }
#pragma unroll
        for (int kk = 0; kk < 32; kk += 16) {
            unsigned int ah[4][4], al[4][4], bh[4][2], bl[4][2];
#pragma unroll
            for (int i = 0; i < 4; i++) {
                unsigned int ad = (unsigned int)((aoff + i * 16 * SMS + kk) * 2);
                LDSM4(ah[i][0], ah[i][1], ah[i][2], ah[i][3], uAh + ad);
                LDSM4(al[i][0], al[i][1], al[i][2], al[i][3], uAl + ad);
            }
#pragma unroll
            for (int j2 = 0; j2 < 2; j2++) {
                unsigned int bd = (unsigned int)((boff + j2 * 16 * SMS + kk) * 2);
                LDSM4(bh[2 * j2][0], bh[2 * j2][1], bh[2 * j2 + 1][0],
                      bh[2 * j2 + 1][1], uBh + bd);
                LDSM4(bl[2 * j2][0], bl[2 * j2][1], bl[2 * j2 + 1][0],
                      bl[2 * j2 + 1][1], uBl + bd);
            }
#pragma unroll
            for (int i = 0; i < 4; i++)
#pragma unroll
                for (int j = 0; j < 4; j++) {
                    MMA_BF16(acc[i][j], ah[i], bh[j]);
                    MMA_BF16(acc[i][j], ah[i], bl[j]);
                    MMA_BF16(acc[i][j], al[i], bh[j]);
                }
        }
        __syncthreads();
    }
#pragma unroll
    for (int i = 0; i < 4; i++) {
        int r0 = bm + m0 + i * 16 + g8;
#pragma unroll
        for (int j = 0; j < 4; j++) {
            int col = bn + n0 + j * 8 + tig * 2;
            *(float2*)(C + (size_t)r0 * N + col) =
                make_float2(acc[i][j][0], acc[i][j][1]);
            *(float2*)(C + (size_t)(r0 + 8) * N + col) =
                make_float2(acc[i][j][2], acc[i][j][3]);
        }
    }
}

// ------------------------- gate = x @ Wgate^T --------------------------------
__global__ void gate_kernel(const float* __restrict__ x,
                            const float* __restrict__ Wg) {
    int t = blockIdx.x;
    int w = threadIdx.x >> 5, lane = threadIdx.x & 31;
    const float* xr = x + (size_t)t * HID;
    const float* wr = Wg + (size_t)w * HID;
    float acc = 0.f;
    for (int i = lane; i < HID; i += 32) acc += xr[i] * wr[i];
#pragma unroll
    for (int off = 16; off; off >>= 1)
        acc += __shfl_xor_sync(0xffffffffu, acc, off);
    if (!lane) g_gate[t * 3 + w] = acc;
}

// ------------------------- RoPE: table + apply --------------------------------
__global__ void rope_table_kernel() {
    int t = blockIdx.x, d = threadIdx.x;
    double inv = exp(-(double)d * (log(10000.0) / 32.0));
    double sn, cs;
    sincos((double)t * inv, &sn, &cs);
    g_cos[t * 32 + d] = (float)cs;
    g_sin[t * 32 + d] = (float)sn;
}

__global__ void rope_apply_kernel(float* x, int nh) {
    int t = blockIdx.x;
    for (int idx = threadIdx.x; idx < nh * 32; idx += blockDim.x) {
        int hh = idx >> 5, d = idx & 31;
        float cs = g_cos[t * 32 + d], sn = g_sin[t * 32 + d];
        float* p = x + ((size_t)t * nh + hh) * D;
        float x1 = p[d], x2 = p[d + 32];
        p[d]      = x1 * cs - x2 * sn;
        p[d + 32] = x2 * cs + x1 * sn;
    }
}

// ------------------------- compression ---------------------------------------
__global__ void compress_kernel(const float* __restrict__ Wck,
                                const float* __restrict__ Wcv) {
    int c = blockIdx.x, g = blockIdx.y, which = blockIdx.z;
    const float* src = which ? g_v : g_k;
    const float* W = (which ? Wcv : Wck) + (size_t)g * 2048 * D;
    float* dst = (which ? g_cv : g_ck) + ((size_t)g * C_NUM + c) * D;
    __shared__ float win[32 * 64];
    for (int i = threadIdx.x; i < 2048; i += blockDim.x) {
        int j = i >> 6, dd = i & 63;
        win[i] = src[((size_t)(16 * c + j) * G + g) * D + dd];
    }
    __syncthreads();
    int d = threadIdx.x;
    float acc = 0.f;
#pragma unroll 4
    for (int f = 0; f < 2048; f++) acc += win[f] * W[(size_t)f * D + d];
    dst[d] = acc;
}

// ------------------------- compressed attention + psum -----------------------
__global__ __launch_bounds__(256) void comp_attn_kernel() {
    int t = blockIdx.x, g = blockIdx.y;
    int tid = threadIdx.x;
    int h = tid >> 4, m16 = tid & 15;
    __shared__ float sq[HG * D];
    __shared__ float sbuf[C_NUM][65];
    __shared__ float sp[HG][128];

    {
        const float4* src = (const float4*)(g_q + ((size_t)t * HQ + g * HG) * D);
        ((float4*)sq)[tid] = src[tid];
    }
    int nc = (t >= 31) ? ((t - 31) >> 4) + 1 : 0;
    float gate0 = 1.f / (1.f + expf(-g_gate[t * 3 + 0]));
    float* psum_out = g_psum + ((size_t)g * T + t) * 128;
    float* out = g_att + ((size_t)t * HQ + g * HG) * D;
    int d0 = m16 << 2;

    if (nc == 0) {
        *(float4*)(out + h * D + d0) = make_float4(0.f, 0.f, 0.f, 0.f);
        if (tid < 128) psum_out[tid] = 0.f;
        return;
    }
    for (int i = tid; i < nc * D; i += 256) {
        int c = i >> 6, d = i & 63;
        sbuf[c][d] = g_ck[((size_t)g * C_NUM + c) * D + d];
    }
    __syncthreads();

    float sv_[8];
    float mx = -INFINITY;
    const float* qh = sq + h * D;
#pragma unroll
    for (int r = 0; r < 8; r++) {
        int c = r * 16 + m16;
        float acc = -INFINITY;
        if (c < nc) {
            acc = 0.f;
#pragma unroll 8
            for (int d = 0; d < D; d++) acc += qh[d] * sbuf[c][d];
            acc *= SCALE;
        }
        sv_[r] = acc;
        mx = fmaxf(mx, acc);
    }
#pragma unroll
    for (int off = 8; off; off >>= 1)
        mx = fmaxf(mx, __shfl_xor_sync(0xffffffffu, mx, off, 16));
    float l = 0.f;
#pragma unroll
    for (int r = 0; r < 8; r++) { sv_[r] = __expf(sv_[r] - mx); l += sv_[r]; }
#pragma unroll
    for (int off = 8; off; off >>= 1)
        l += __shfl_xor_sync(0xffffffffu, l, off, 16);
    float invl = 1.f / l;
#pragma unroll
    for (int r = 0; r < 8; r++) sp[h][r * 16 + m16] = sv_[r] * invl;
    __syncthreads();

    if (tid < 128) {
        float s = 0.f;
        if (tid < nc) {
#pragma unroll
            for (int hh = 0; hh < HG; hh++) s += sp[hh][tid];
        }
        psum_out[tid] = s;
    }
    for (int i = tid; i < nc * D; i += 256) {
        int c = i >> 6, d = i & 63;
        sbuf[c][d] = g_cv[((size_t)g * C_NUM + c) * D + d];
    }
    __syncthreads();

    float a0 = 0, a1 = 0, a2 = 0, a3 = 0;
    for (int c = 0; c < nc; c++) {
        float p = sp[h][c];
        a0 += p * sbuf[c][d0 + 0];
        a1 += p * sbuf[c][d0 + 1];
        a2 += p * sbuf[c][d0 + 2];
        a3 += p * sbuf[c][d0 + 3];
    }
    out[h * D + d0 + 0] = gate0 * a0;
    out[h * D + d0 + 1] = gate0 * a1;
    out[h * D + d0 + 2] = gate0 * a2;
    out[h * D + d0 + 3] = gate0 * a3;
}

// ------------------------- block score + stable top-k ------------------------
__global__ void select_kernel() {
    int t = blockIdx.x, g = blockIdx.y;
    int b = threadIdx.x;
    const float* ps = g_psum + ((size_t)g * T + t) * 128;
    float sc = 0.f;
    int clo = 4 * b - 1; if (clo < 0) clo = 0;
    int chi = 4 * b + 3; if (chi > C_NUM - 1) chi = C_NUM - 1;
    for (int c = clo; c <= chi; c++) sc += ps[c];
    int qb = t >> 6;
    bool causal = (b <= qb);
    bool forced = (b < 1) || ((qb - b < 2) && causal);
    float val = causal ? (forced ? INFINITY : sc) : -INFINITY;
    unsigned selbits = 0;
    for (int it = 0; it < TOPK; it++) {
        float rv = val; int ri = b;
#pragma unroll
        for (int off = 16; off; off >>= 1) {
            float ov = __shfl_xor_sync(0xffffffffu, rv, off);
            int oi = __shfl_xor_sync(0xffffffffu, ri, off);
            if (ov > rv || (ov == rv && oi < ri)) { rv = ov; ri = oi; }
        }
        if (rv == -INFINITY) break;
        selbits |= (1u << ri);
        if (b == ri) val = -INFINITY;
    }
    if (b == 0) g_sel[(size_t)g * T + t] = selbits;
}

// ------------------------- MMA flash attention (sparse + sliding) ------------
// 8 warps: warps 0-3 sparse branch, warps 4-7 sliding branch.
// Each warp: private online softmax over its subset of 64-key blocks.
__global__ __launch_bounds__(256) void attn_mma_kernel() {
    int t = blockIdx.x, g = blockIdx.y;
    int tid = threadIdx.x;
    int warp = tid >> 5, lane = tid & 31;
    int g8 = lane >> 2, tig = lane & 3;
    int mode = warp >> 2, w4 = warp & 3;

    __shared__ float sm_m[8][16];
    __shared__ float sm_l[8][16];
    __shared__ float sacc[8][16][64];

    int qb = t >> 6;
    int lo = t - WINDOW; if (lo < 0) lo = 0;
    unsigned mask;
    if (mode == 0) mask = g_sel[(size_t)g * T + t];
    else mask = ((2u << qb) - 1) & ~((1u << (lo >> 6)) - 1);

    // q fragments hi/lo, 4 k-chunks of 16 dims
    unsigned aqh[4][4], aql[4][4];
    {
        const float* qbase = g_q + ((size_t)t * HQ + g * HG) * D;
#pragma unroll
        for (int c = 0; c < 4; c++) {
            int d0 = c * 16 + 2 * tig;
            float2 v00 = *(const float2*)(qbase + g8 * D + d0);
            float2 v10 = *(const float2*)(qbase + (g8 + 8) * D + d0);
            float2 v01 = *(const float2*)(qbase + g8 * D + d0 + 8);
            float2 v11 = *(const float2*)(qbase + (g8 + 8) * D + d0 + 8);
            split2(v00.x, v00.y, aqh[c][0], aql[c][0]);
            split2(v10.x, v10.y, aqh[c][1], aql[c][1]);
            split2(v01.x, v01.y, aqh[c][2], aql[c][2]);
            split2(v11.x, v11.y, aqh[c][3], aql[c][3]);
        }
    }

    float m0 = -INFINITY, m1 = -INFINITY, l0 = 0.f, l1 = 0.f;
    float acc[8][4];
#pragma unroll
    for (int j = 0; j < 8; j++)
#pragma unroll
        for (int r = 0; r < 4; r++) acc[j][r] = 0.f;

    unsigned rem = mask;
    int bidx = 0;
    while (rem) {
        int b = __ffs(rem) - 1;
        rem &= rem - 1;
        if ((bidx++ & 3) != w4) continue;
        int sbase = b << 6;
        int smax = t - sbase; if (smax > 63) smax = 63;
        int smin = 0;
        if (mode == 1) { smin = lo - sbase; if (smin < 0) smin = 0; }

        // ----- QK: S[16 x 64] -----
        float S[8][4];
#pragma unroll
        for (int j = 0; j < 8; j++)
#pragma unroll
            for (int r = 0; r < 4; r++) S[j][r] = 0.f;

        const __nv_bfloat16* kbh =
            g_kh + ((size_t)(sbase + g8) * G + g) * D + 2 * tig;
        const __nv_bfloat16* kbl =
            g_kl + ((size_t)(sbase + g8) * G + g) * D + 2 * tig;
#pragma unroll
        for (int j = 0; j < 8; j++) {
            const __nv_bfloat16* ph_ = kbh + (size_t)j * 8 * (G * D);
            const __nv_bfloat16* pl_ = kbl + (size_t)j * 8 * (G * D);
#pragma unroll
            for (int c = 0; c < 4; c++) {
                unsigned bh[2], bl[2];
                bh[0] = *(const unsigned*)(ph_ + 16 * c);
                bh[1] = *(const unsigned*)(ph_ + 16 * c + 8);
                bl[0] = *(const unsigned*)(pl_ + 16 * c);
                bl[1] = *(const unsigned*)(pl_ + 16 * c + 8);
                MMA_BF16(S[j], aqh[c], bh);
                MMA_BF16(S[j], aql[c], bh);
                MMA_BF16(S[j], aqh[c], bl);
            }
        }
        // mask + scale + per-block row max
        float bmax0 = -INFINITY, bmax1 = -INFINITY;
        int soff = 2 * tig;
#pragma unroll
        for (int j = 0; j < 8; j++) {
            int s0i = 8 * j + soff, s1i = s0i + 1;
            bool v0 = (s0i >= smin) && (s0i <= smax);
            bool v1 = (s1i >= smin) && (s1i <= smax);
            S[j][0] = v0 ? S[j][0] * SCALE : -INFINITY;
            S[j][1] = v1 ? S[j][1] * SCALE : -INFINITY;
            S[j][2] = v0 ? S[j][2] * SCALE : -INFINITY;
            S[j][3] = v1 ? S[j][3] * SCALE : -INFINITY;
            bmax0 = fmaxf(bmax0, fmaxf(S[j][0], S[j][1]));
            bmax1 = fmaxf(bmax1, fmaxf(S[j][2], S[j][3]));
        }
        bmax0 = fmaxf(bmax0, __shfl_xor_sync(0xffffffffu, bmax0, 1));
        bmax0 = fmaxf(bmax0, __shfl_xor_sync(0xffffffffu, bmax0, 2));
        bmax1 = fmaxf(bmax1, __shfl_xor_sync(0xffffffffu, bmax1, 1));
        bmax1 = fmaxf(bmax1, __shfl_xor_sync(0xffffffffu, bmax1, 2));
        float mn0 = fmaxf(m0, bmax0), mn1 = fmaxf(m1, bmax1);
        float cor0 = __expf(m0 - mn0), cor1 = __expf(m1 - mn1);
        m0 = mn0; m1 = mn1;

        unsigned ph0[8], ph1[8], pl0[8], pl1[8];
        float ps0 = 0.f, ps1 = 0.f;
#pragma unroll
        for (int j = 0; j < 8; j++) {
            float p0 = __expf(S[j][0] - mn0);
            float p1 = __expf(S[j][1] - mn0);
            float p2 = __expf(S[j][2] - mn1);
            float p3 = __expf(S[j][3] - mn1);
            ps0 += p0 + p1;
            ps1 += p2 + p3;
            split2(p0, p1, ph0[j], pl0[j]);
            split2(p2, p3, ph1[j], pl1[j]);
        }
        ps0 += __shfl_xor_sync(0xffffffffu, ps0, 1);
        ps0 += __shfl_xor_sync(0xffffffffu, ps0, 2);
        ps1 += __shfl_xor_sync(0xffffffffu, ps1, 1);
        ps1 += __shfl_xor_sync(0xffffffffu, ps1, 2);
        l0 = l0 * cor0 + ps0;
        l1 = l1 * cor1 + ps1;
#pragma unroll
        for (int j = 0; j < 8; j++) {
            acc[j][0] *= cor0; acc[j][1] *= cor0;
            acc[j][2] *= cor1; acc[j][3] *= cor1;
        }

        // ----- PV: acc += P @ V -----
        const __nv_bfloat16* vbh =
            g_vth + ((size_t)(g * D + g8)) * T + sbase + 2 * tig;
        const __nv_bfloat16* vbl =
            g_vtl + ((size_t)(g * D + g8)) * T + sbase + 2 * tig;
#pragma unroll
        for (int jd = 0; jd < 8; jd++) {
            const __nv_bfloat16* pvh = vbh + (size_t)jd * 8 * T;
            const __nv_bfloat16* pvl = vbl + (size_t)jd * 8 * T;
#pragma unroll
            for (int kc = 0; kc < 4; kc++) {
                unsigned bh[2], bl[2];
                bh[0] = *(const unsigned*)(pvh + 16 * kc);
                bh[1] = *(const unsigned*)(pvh + 16 * kc + 8);
                bl[0] = *(const unsigned*)(pvl + 16 * kc);
                bl[1] = *(const unsigned*)(pvl + 16 * kc + 8);
                unsigned ah[4] = {ph0[2 * kc], ph1[2 * kc],
                                  ph0[2 * kc + 1], ph1[2 * kc + 1]};
                unsigned al_[4] = {pl0[2 * kc], pl1[2 * kc],
                                   pl0[2 * kc + 1], pl1[2 * kc + 1]};
                MMA_BF16(acc[jd], ah, bh);
                MMA_BF16(acc[jd], al_, bh);
                MMA_BF16(acc[jd], ah, bl);
            }
        }
    }

    // per-warp state to smem
    if (tig == 0) {
        sm_m[warp][g8] = m0; sm_m[warp][g8 + 8] = m1;
        sm_l[warp][g8] = l0; sm_l[warp][g8 + 8] = l1;
    }
#pragma unroll
    for (int j = 0; j < 8; j++) {
        sacc[warp][g8][8 * j + 2 * tig] = acc[j][0];
        sacc[warp][g8][8 * j + 2 * tig + 1] = acc[j][1];
        sacc[warp][g8 + 8][8 * j + 2 * tig] = acc[j][2];
        sacc[warp][g8 + 8][8 * j + 2 * tig + 1] = acc[j][3];
    }
    __syncthreads();

    // merge the 4 partials of each branch; combine with gates
    int row = tid >> 4, col = (tid & 15) << 2;
    float M1 = sm_m[0][row], M2 = sm_m[4][row];
#pragma unroll
    for (int w = 1; w < 4; w++) {
        M1 = fmaxf(M1, sm_m[w][row]);
        M2 = fmaxf(M2, sm_m[4 + w][row]);
    }
    float L1 = 0.f, L2 = 0.f;
    float o1[4] = {0, 0, 0, 0}, o2[4] = {0, 0, 0, 0};
#pragma unroll
    for (int w = 0; w < 4; w++) {
        float f1 = __expf(sm_m[w][row] - M1);
        float f2 = __expf(sm_m[4 + w][row] - M2);
        L1 += f1 * sm_l[w][row];
        L2 += f2 * sm_l[4 + w][row];
        const float* a1 = &sacc[w][row][col];
        const float* a2 = &sacc[4 + w][row][col];
#pragma unroll
        for (int e = 0; e < 4; e++) {
            o1[e] += f1 * a1[e];
            o2[e] += f2 * a2[e];
        }
    }
    float gg1 = 1.f / (1.f + expf(-g_gate[t * 3 + 1]));
    float gg2 = 1.f / (1.f + expf(-g_gate[t * 3 + 2]));
    float w1 = gg1 / L1, w2 = gg2 / L2;
    float* op = g_att + ((size_t)t * HQ + g * HG + row) * D + col;
    float4 cur = *(float4*)op;
    cur.x += w1 * o1[0] + w2 * o2[0];
    cur.y += w1 * o1[1] + w2 * o2[1];
    cur.z += w1 * o1[2] + w2 * o2[2];
    cur.w += w1 * o1[3] + w2 * o2[3];
    *(float4*)op = cur;
}

// ------------------------- launch --------------------------------------------
extern "C" void kernel_launch(void* const* d_in, const int* in_sizes, int n_in,
                              void* d_out, int out_size) {
    const float* x   = (const float*)d_in[0];
    const float* Wq  = (const float*)d_in[1];
    const float* Wk  = (const float*)d_in[2];
    const float* Wv  = (const float*)d_in[3];
    const float* Wo  = (const float*)d_in[4];
    const float* Wg  = (const float*)d_in[5];
    const float* Wck = (const float*)d_in[6];
    const float* Wcv = (const float*)d_in[7];
    float* out = (float*)d_out;

    float *pq, *pk, *pv, *patt;
    cudaGetSymbolAddress((void**)&pq, g_q);
    cudaGetSymbolAddress((void**)&pk, g_k);
    cudaGetSymbolAddress((void**)&pv, g_v);
    cudaGetSymbolAddress((void**)&patt, g_att);
    __nv_bfloat16 *xh, *xl, *wqh, *wql, *wkh, *wkl, *wvh, *wvl, *woh, *wol,
        *ath, *atl;
    cudaGetSymbolAddress((void**)&xh, g_xh);
    cudaGetSymbolAddress((void**)&xl, g_xl);
    cudaGetSymbolAddress((void**)&wqh, g_wqh);
    cudaGetSymbolAddress((void**)&wql, g_wql);
    cudaGetSymbolAddress((void**)&wkh, g_wkh);
    cudaGetSymbolAddress((void**)&wkl, g_wkl);
    cudaGetSymbolAddress((void**)&wvh, g_wvh);
    cudaGetSymbolAddress((void**)&wvl, g_wvl);
    cudaGetSymbolAddress((void**)&woh, g_woh);
    cudaGetSymbolAddress((void**)&wol, g_wol);
    cudaGetSymbolAddress((void**)&ath, g_ath);
    cudaGetSymbolAddress((void**)&atl, g_atl);

    const int NELT = T * HID;
    const int NKV = G * D * HID;
    split_kernel<<<NELT / 1024, 256>>>(x, xh, xl, NELT);
    split_kernel<<<NELT / 1024, 256>>>(Wq, wqh, wql, NELT);
    split_kernel<<<NKV / 1024, 256>>>(Wk, wkh, wkl, NKV);
    split_kernel<<<NKV / 1024, 256>>>(Wv, wvh, wvl, NKV);
    split_kernel<<<NELT / 1024, 256>>>(Wo, woh, wol, NELT);
    rope_table_kernel<<<T, 32>>>();

    gemm_bf16x3<<<dim3((HQ * D) / 128, T / 128, 1), 256>>>(
        xh, xl, wqh, wql, pq, wqh, wql, pq, T, HQ * D, HID);
    gemm_bf16x3<<<dim3(1, T / 128, 2), 256>>>(
        xh, xl, wkh, wkl, pk, wvh, wvl, pv, T, G * D, HID);
    gate_kernel<<<T, 96>>>(x, Wg);
    rope_apply_kernel<<<T, 256>>>(pq, HQ);
    rope_apply_kernel<<<T, 64>>>(pk, G);
    kvsplit_kernel<<<(T * G * D) / 256, 256>>>();
    compress_kernel<<<dim3(C_NUM, G, 2), 64>>>(Wck, Wcv);
    comp_attn_kernel<<<dim3(T, G), 256>>>();
    select_kernel<<<dim3(T, G), 32>>>();
    attn_mma_kernel<<<dim3(T, G), 256>>>();

    split_kernel<<<NELT / 1024, 256>>>(patt, ath, atl, NELT);
    gemm_bf16x3<<<dim3(HID / 128, T / 128, 1), 256>>>(
        ath, atl, woh, wol, out, woh, wol, out, T, HID, HID);
}

// round 6
// speedup vs baseline: 4.2820x; 1.5702x over previous
#include <cuda_runtime.h>
#include <cuda_bf16.h>
#include <math.h>
#include <stdint.h>

#define T 2048
#define HID 2048
#define HQ 32
#define G 2
#define D 64
#define HG 16          // HQ / G
#define C_NUM 127      // compressed windows
#define TOPK 16
#define WINDOW 512
#define SCALE 0.125f

// ------------------------- scratch (device globals; no allocs) --------------
__device__ float g_q[T * HQ * D];
__device__ float g_k[T * G * D];
__device__ float g_v[T * G * D];
__device__ float g_gate[T * 3];
__device__ float g_ck[G * C_NUM * D];
__device__ float g_cv[G * C_NUM * D];
__device__ float g_psum[G * T * 128];
__device__ unsigned g_sel[G * T];
__device__ float g_att[T * HQ * D];
__device__ float g_cos[T * 32];
__device__ float g_sin[T * 32];

// bf16 split buffers
__device__ __align__(16) __nv_bfloat16 g_xh[T * HID];
__device__ __align__(16) __nv_bfloat16 g_xl[T * HID];
__device__ __align__(16) __nv_bfloat16 g_wqh[HQ * D * HID];
__device__ __align__(16) __nv_bfloat16 g_wql[HQ * D * HID];
__device__ __align__(16) __nv_bfloat16 g_wkh[G * D * HID];
__device__ __align__(16) __nv_bfloat16 g_wkl[G * D * HID];
__device__ __align__(16) __nv_bfloat16 g_wvh[G * D * HID];
__device__ __align__(16) __nv_bfloat16 g_wvl[G * D * HID];
__device__ __align__(16) __nv_bfloat16 g_woh[HID * HID];
__device__ __align__(16) __nv_bfloat16 g_wol[HID * HID];
__device__ __align__(16) __nv_bfloat16 g_ath[T * HID];
__device__ __align__(16) __nv_bfloat16 g_atl[T * HID];
// attention K/V bf16 hi/lo, FRAGMENT-PERMUTED layouts
// K: [t][g][d'] with d' permuted; V^T: [g][d][t'] with t' permuted per 64-block
__device__ __align__(16) __nv_bfloat16 g_kh[T * G * D];
__device__ __align__(16) __nv_bfloat16 g_kl[T * G * D];
__device__ __align__(16) __nv_bfloat16 g_vth[G * D * T];
__device__ __align__(16) __nv_bfloat16 g_vtl[G * D * T];

// ------------------------- helpers ------------------------------------------
__device__ __forceinline__ void split2(float x, float y, unsigned& h,
                                       unsigned& l) {
    __nv_bfloat162 hh = __floats2bfloat162_rn(x, y);
    float hx = __bfloat162float(__low2bfloat16(hh));
    float hy = __bfloat162float(__high2bfloat16(hh));
    __nv_bfloat162 ll = __floats2bfloat162_rn(x - hx, y - hy);
    h = *reinterpret_cast<unsigned*>(&hh);
    l = *reinterpret_cast<unsigned*>(&ll);
}

// fragment permutation on bf162 index o (0..31): p = (o&3)*8+(o>>3)*2+((o>>2)&1)
__device__ __forceinline__ int frag_perm(int o) {
    return ((o & 3) << 3) + ((o >> 3) << 1) + ((o >> 2) & 1);
}

// ------------------------- fp32 -> bf16 hi/lo split --------------------------
__global__ void split_kernel(const float* __restrict__ src,
                             __nv_bfloat16* __restrict__ hi,
                             __nv_bfloat16* __restrict__ lo, int n) {
    int i = (blockIdx.x * blockDim.x + threadIdx.x) * 4;
    if (i >= n) return;
    float4 v = *(const float4*)(src + i);
    unsigned h0, l0, h1, l1;
    split2(v.x, v.y, h0, l0);
    split2(v.z, v.w, h1, l1);
    ((unsigned*)(hi + i))[0] = h0;
    ((unsigned*)(hi + i))[1] = h1;
    ((unsigned*)(lo + i))[0] = l0;
    ((unsigned*)(lo + i))[1] = l1;
}

// K split (permuted d) + V transpose/split (permuted t within 64-block)
__global__ void kvsplit_kernel() {
    int i = blockIdx.x * blockDim.x + threadIdx.x;  // over T*G*D
    int d = i & 63;
    float kv = g_k[i];
    __nv_bfloat16 h = __float2bfloat16(kv);
    int nd = (frag_perm(d >> 1) << 1) + (d & 1);
    g_kh[(i - d) + nd] = h;
    g_kl[(i - d) + nd] = __float2bfloat16(kv - __bfloat162float(h));

    int t = i >> 7, gd = i & 127;
    float vv = g_v[i];
    __nv_bfloat16 vh = __float2bfloat16(vv);
    int tt = t & 63;
    int nt = (t & ~63) + (frag_perm(tt >> 1) << 1) + (tt & 1);
    int o = gd * T + nt;
    g_vth[o] = vh;
    g_vtl[o] = __float2bfloat16(vv - __bfloat162float(vh));
}

// ------------------------- MMA macros ----------------------------------------
#define SMS 40

#define LDSM4(r0, r1, r2, r3, addr)                                       \
    asm volatile("ldmatrix.sync.aligned.m8n8.x4.shared.b16 "              \
                 "{%0,%1,%2,%3}, [%4];"                                   \
                 : "=r"(r0), "=r"(r1), "=r"(r2), "=r"(r3) : "r"(addr))

#define MMA_BF16(dd, aa, bb)                                              \
    asm volatile("mma.sync.aligned.m16n8k16.row.col.f32.bf16.bf16.f32 "   \
                 "{%0,%1,%2,%3},{%4,%5,%6,%7},{%8,%9},{%0,%1,%2,%3};"     \
                 : "+f"(dd[0]), "+f"(dd[1]), "+f"(dd[2]), "+f"(dd[3])     \
                 : "r"(aa[0]), "r"(aa[1]), "r"(aa[2]), "r"(aa[3]),        \
                   "r"(bb[0]), "r"(bb[1]))

// ------------------------- QKV fused GEMM (x @ [Wq|Wk|Wv]^T) -----------------
// grid (18, 16): bx 0..15 -> Wq tile -> g_q; bx==16 -> Wk -> g_k; 17 -> Wv -> g_v
__global__ __launch_bounds__(256) void gemm_qkv() {
    __shared__ __nv_bfloat16 sAh[128 * SMS], sAl[128 * SMS];
    __shared__ __nv_bfloat16 sBh[128 * SMS], sBl[128 * SMS];

    const int K = HID;
    int bx = blockIdx.x;
    const __nv_bfloat16 *Bh, *Bl;
    float* C;
    int ldc, bnw, bnc;
    if (bx < 16) {
        Bh = g_wqh; Bl = g_wql; C = g_q; ldc = HQ * D;
        bnw = bx * 128; bnc = bx * 128;
    } else if (bx == 16) {
        Bh = g_wkh; Bl = g_wkl; C = g_k; ldc = G * D; bnw = 0; bnc = 0;
    } else {
        Bh = g_wvh; Bl = g_wvl; C = g_v; ldc = G * D; bnw = 0; bnc = 0;
    }

    int tid = threadIdx.x;
    int bm = blockIdx.y * 128;
    int lrow = tid >> 1, lcol = (tid & 1) << 4;
    int wid = tid >> 5, lane = tid & 31;
    int wm = wid & 1, wn = wid >> 1;
    int m0 = wm * 64, n0 = wn * 32;
    int g8 = lane >> 2, tig = lane & 3;

    const __nv_bfloat16* pAh = g_xh + (size_t)(bm + lrow) * K + lcol;
    const __nv_bfloat16* pAl = g_xl + (size_t)(bm + lrow) * K + lcol;
    const __nv_bfloat16* pBh = Bh + (size_t)(bnw + lrow) * K + lcol;
    const __nv_bfloat16* pBl = Bl + (size_t)(bnw + lrow) * K + lcol;

    float acc[4][4][4];
#pragma unroll
    for (int i = 0; i < 4; i++)
#pragma unroll
        for (int j = 0; j < 4; j++)
#pragma unroll
            for (int r = 0; r < 4; r++) acc[i][j][r] = 0.f;

    int aoff = (m0 + (lane & 7) + ((lane >> 3) & 1) * 8) * SMS + (lane >> 4) * 8;
    int boff = (n0 + (lane & 7) + (lane >> 4) * 8) * SMS + ((lane >> 3) & 1) * 8;
    unsigned int uAh = (unsigned int)__cvta_generic_to_shared(sAh);
    unsigned int uAl = (unsigned int)__cvta_generic_to_shared(sAl);
    unsigned int uBh = (unsigned int)__cvta_generic_to_shared(sBh);
    unsigned int uBl = (unsigned int)__cvta_generic_to_shared(sBl);

    uint4 vah0, vah1, val0, val1, vbh0, vbh1, vbl0, vbl1;
    vah0 = *(const uint4*)(pAh);     vah1 = *(const uint4*)(pAh + 8);
    val0 = *(const uint4*)(pAl);     val1 = *(const uint4*)(pAl + 8);
    vbh0 = *(const uint4*)(pBh);     vbh1 = *(const uint4*)(pBh + 8);
    vbl0 = *(const uint4*)(pBl);     vbl1 = *(const uint4*)(pBl + 8);

    int sidx = lrow * SMS + lcol;
    for (int k0 = 0; k0 < K; k0 += 32) {
        *(uint4*)&sAh[sidx] = vah0; *(uint4*)&sAh[sidx + 8] = vah1;
        *(uint4*)&sAl[sidx] = val0; *(uint4*)&sAl[sidx + 8] = val1;
        *(uint4*)&sBh[sidx] = vbh0; *(uint4*)&sBh[sidx + 8] = vbh1;
        *(uint4*)&sBl[sidx] = vbl0; *(uint4*)&sBl[sidx + 8] = vbl1;
        __syncthreads();
        if (k0 + 32 < K) {
            int kn = k0 + 32;
            vah0 = *(const uint4*)(pAh + kn); vah1 = *(const uint4*)(pAh + kn + 8);
            val0 = *(const uint4*)(pAl + kn); val1 = *(const uint4*)(pAl + kn + 8);
            vbh0 = *(const uint4*)(pBh + kn); vbh1 = *(const uint4*)(pBh + kn + 8);
            vbl0 = *(const uint4*)(pBl + kn); vbl1 = *(const uint4*)(pBl + kn + 8);
        }
#pragma unroll
        for (int kk = 0; kk < 32; kk += 16) {
            unsigned int ah[4][4], al[4][4], bh[4][2], bl[4][2];
#pragma unroll
            for (int i = 0; i < 4; i++) {
                unsigned int ad = (unsigned int)((aoff + i * 16 * SMS + kk) * 2);
                LDSM4(ah[i][0], ah[i][1], ah[i][2], ah[i][3], uAh + ad);
                LDSM4(al[i][0], al[i][1], al[i][2], al[i][3], uAl + ad);
            }
#pragma unroll
            for (int j2 = 0; j2 < 2; j2++) {
                unsigned int bd = (unsigned int)((boff + j2 * 16 * SMS + kk) * 2);
                LDSM4(bh[2 * j2][0], bh[2 * j2][1], bh[2 * j2 + 1][0],
                      bh[2 * j2 + 1][1], uBh + bd);
                LDSM4(bl[2 * j2][0], bl[2 * j2][1], bl[2 * j2 + 1][0],
                      bl[2 * j2 + 1][1], uBl + bd);
            }
#pragma unroll
            for (int i = 0; i < 4; i++)
#pragma unroll
                for (int j = 0; j < 4; j++) {
                    MMA_BF16(acc[i][j], ah[i], bh[j]);
                    MMA_BF16(acc[i][j], ah[i], bl[j]);
                    MMA_BF16(acc[i][j], al[i], bh[j]);
                }
        }
        __syncthreads();
    }
#pragma unroll
    for (int i = 0; i < 4; i++) {
        int r0 = bm + m0 + i * 16 + g8;
#pragma unroll
        for (int j = 0; j < 4; j++) {
            int col = bnc + n0 + j * 8 + tig * 2;
            *(float2*)(C + (size_t)r0 * ldc + col) =
                make_float2(acc[i][j][0], acc[i][j][1]);
            *(float2*)(C + (size_t)(r0 + 8) * ldc + col) =
                make_float2(acc[i][j][2], acc[i][j][3]);
        }
    }
}

// ------------------------- generic bf16x3 GEMM (Wo) ---------------------------
__global__ __launch_bounds__(256) void gemm_bf16x3(
    const __nv_bfloat16* __restrict__ Ah, const __nv_bfloat16* __restrict__ Al,
    const __nv_bfloat16* __restrict__ Bh, const __nv_bfloat16* __restrict__ Bl,
    float* __restrict__ C, int M, int N, int K) {
    __shared__ __nv_bfloat16 sAh[128 * SMS], sAl[128 * SMS];
    __shared__ __nv_bfloat16 sBh[128 * SMS], sBl[128 * SMS];

    int tid = threadIdx.x;
    int bm = blockIdx.y * 128, bn = blockIdx.x * 128;
    int lrow = tid >> 1, lcol = (tid & 1) << 4;
    int wid = tid >> 5, lane = tid & 31;
    int wm = wid & 1, wn = wid >> 1;
    int m0 = wm * 64, n0 = wn * 32;
    int g8 = lane >> 2, tig = lane & 3;

    const __nv_bfloat16* pAh = Ah + (size_t)(bm + lrow) * K + lcol;
    const __nv_bfloat16* pAl = Al + (size_t)(bm + lrow) * K + lcol;
    const __nv_bfloat16* pBh = Bh + (size_t)(bn + lrow) * K + lcol;
    const __nv_bfloat16* pBl = Bl + (size_t)(bn + lrow) * K + lcol;

    float acc[4][4][4];
#pragma unroll
    for (int i = 0; i < 4; i++)
#pragma unroll
        for (int j = 0; j < 4; j++)
#pragma unroll
            for (int r = 0; r < 4; r++) acc[i][j][r] = 0.f;

    int aoff = (m0 + (lane & 7) + ((lane >> 3) & 1) * 8) * SMS + (lane >> 4) * 8;
    int boff = (n0 + (lane & 7) + (lane >> 4) * 8) * SMS + ((lane >> 3) & 1) * 8;
    unsigned int uAh = (unsigned int)__cvta_generic_to_shared(sAh);
    unsigned int uAl = (unsigned int)__cvta_generic_to_shared(sAl);
    unsigned int uBh = (unsigned int)__cvta_generic_to_shared(sBh);
    unsigned int uBl = (unsigned int)__cvta_generic_to_shared(sBl);

    uint4 vah0, vah1, val0, val1, vbh0, vbh1, vbl0, vbl1;
    vah0 = *(const uint4*)(pAh);     vah1 = *(const uint4*)(pAh + 8);
    val0 = *(const uint4*)(pAl);     val1 = *(const uint4*)(pAl + 8);
    vbh0 = *(const uint4*)(pBh);     vbh1 = *(const uint4*)(pBh + 8);
    vbl0 = *(const uint4*)(pBl);     vbl1 = *(const uint4*)(pBl + 8);

    int sidx = lrow * SMS + lcol;
    for (int k0 = 0; k0 < K; k0 += 32) {
        *(uint4*)&sAh[sidx] = vah0; *(uint4*)&sAh[sidx + 8] = vah1;
        *(uint4*)&sAl[sidx] = val0; *(uint4*)&sAl[sidx + 8] = val1;
        *(uint4*)&sBh[sidx] = vbh0; *(uint4*)&sBh[sidx + 8] = vbh1;
        *(uint4*)&sBl[sidx] = vbl0; *(uint4*)&sBl[sidx + 8] = vbl1;
        __syncthreads();
        if (k0 + 32 < K) {
            int kn = k0 + 32;
            vah0 = *(const uint4*)(pAh + kn); vah1 = *(const uint4*)(pAh + kn + 8);
            val0 = *(const uint4*)(pAl + kn); val1 = *(const uint4*)(pAl + kn + 8);
            vbh0 = *(const uint4*)(pBh + kn); vbh1 = *(const uint4*)(pBh + kn + 8);
            vbl0 = *(const uint4*)(pBl + kn); vbl1 = *(const uint4*)(pBl + kn + 8);
        }
#pragma unroll
        for (int kk = 0; kk < 32; kk += 16) {
            unsigned int ah[4][4], al[4][4], bh[4][2], bl[4][2];
#pragma unroll
            for (int i = 0; i < 4; i++) {
                unsigned int ad = (unsigned int)((aoff + i * 16 * SMS + kk) * 2);
                LDSM4(ah[i][0], ah[i][1], ah[i][2], ah[i][3], uAh + ad);
                LDSM4(al[i][0], al[i][1], al[i][2], al[i][3], uAl + ad);
            }
#pragma unroll
            for (int j2 = 0; j2 < 2; j2++) {
                unsigned int bd = (unsigned int)((boff + j2 * 16 * SMS + kk) * 2);
                LDSM4(bh[2 * j2][0], bh[2 * j2][1], bh[2 * j2 + 1][0],
                      bh[2 * j2 + 1][1], uBh + bd);
                LDSM4(bl[2 * j2][0], bl[2 * j2][1], bl[2 * j2 + 1][0],
                      bl[2 * j2 + 1][1], uBl + bd);
            }
#pragma unroll
            for (int i = 0; i < 4; i++)
#pragma unroll
                for (int j = 0; j < 4; j++) {
                    MMA_BF16(acc[i][j], ah[i], bh[j]);
                    MMA_BF16(acc[i][j], ah[i], bl[j]);
                    MMA_BF16(acc[i][j], al[i], bh[j]);
                }
        }
        __syncthreads();
    }
#pragma unroll
    for (int i = 0; i < 4; i++) {
        int r0 = bm + m0 + i * 16 + g8;
#pragma unroll
        for (int j = 0; j < 4; j++) {
            int col = bn + n0 + j * 8 + tig * 2;
            *(float2*)(C + (size_t)r0 * N + col) =
                make_float2(acc[i][j][0], acc[i][j][1]);
            *(float2*)(C + (size_t)(r0 + 8) * N + col) =
                make_float2(acc[i][j][2], acc[i][j][3]);
        }
    }
}

// ------------------------- gate = x @ Wgate^T --------------------------------
__global__ void gate_kernel(const float* __restrict__ x,
                            const float* __restrict__ Wg) {
    int t = blockIdx.x;
    int w = threadIdx.x >> 5, lane = threadIdx.x & 31;
    const float* xr = x + (size_t)t * HID;
    const float* wr = Wg + (size_t)w * HID;
    float acc = 0.f;
    for (int i = lane; i < HID; i += 32) acc += xr[i] * wr[i];
#pragma unroll
    for (int off = 16; off; off >>= 1)
        acc += __shfl_xor_sync(0xffffffffu, acc, off);
    if (!lane) g_gate[t * 3 + w] = acc;
}

// ------------------------- RoPE: table + apply --------------------------------
__global__ void rope_table_kernel() {
    int t = blockIdx.x, d = threadIdx.x;
    double inv = exp(-(double)d * (log(10000.0) / 32.0));
    double sn, cs;
    sincos((double)t * inv, &sn, &cs);
    g_cos[t * 32 + d] = (float)cs;
    g_sin[t * 32 + d] = (float)sn;
}

__global__ void rope_apply_kernel(float* x, int nh) {
    int t = blockIdx.x;
    for (int idx = threadIdx.x; idx < nh * 32; idx += blockDim.x) {
        int hh = idx >> 5, d = idx & 31;
        float cs = g_cos[t * 32 + d], sn = g_sin[t * 32 + d];
        float* p = x + ((size_t)t * nh + hh) * D;
        float x1 = p[d], x2 = p[d + 32];
        p[d]      = x1 * cs - x2 * sn;
        p[d + 32] = x2 * cs + x1 * sn;
    }
}

// ------------------------- compression (4-way f-split) -----------------------
__global__ __launch_bounds__(256) void compress_kernel(
    const float* __restrict__ Wck, const float* __restrict__ Wcv) {
    int c = blockIdx.x, g = blockIdx.y, which = blockIdx.z;
    const float* src = which ? g_v : g_k;
    const float* W = (which ? Wcv : Wck) + (size_t)g * 2048 * D;
    float* dst = (which ? g_cv : g_ck) + ((size_t)g * C_NUM + c) * D;
    __shared__ float win[32 * 64];
    __shared__ float partial[4][64];
    int tid = threadIdx.x;
    for (int i = tid; i < 2048; i += 256) {
        int j = i >> 6, dd = i & 63;
        win[i] = src[((size_t)(16 * c + j) * G + g) * D + dd];
    }
    __syncthreads();
    int d = tid & 63, q = tid >> 6;
    float acc = 0.f;
    const float* Wp = W + (size_t)(q * 512) * D + d;
    const float* wp = win + q * 512;
#pragma unroll 8
    for (int f = 0; f < 512; f++) acc += wp[f] * Wp[(size_t)f * D];
    partial[q][d] = acc;
    __syncthreads();
    if (tid < 64)
        dst[tid] = partial[0][tid] + partial[1][tid] + partial[2][tid] +
                   partial[3][tid];
}

// ------------------------- compressed attention + psum -----------------------
__global__ __launch_bounds__(256) void comp_attn_kernel() {
    int t = blockIdx.x, g = blockIdx.y;
    int tid = threadIdx.x;
    int h = tid >> 4, m16 = tid & 15;
    __shared__ float sq[HG * D];
    __shared__ float sbuf[C_NUM][65];
    __shared__ float sp[HG][128];

    {
        const float4* src = (const float4*)(g_q + ((size_t)t * HQ + g * HG) * D);
        ((float4*)sq)[tid] = src[tid];
    }
    int nc = (t >= 31) ? ((t - 31) >> 4) + 1 : 0;
    float gate0 = 1.f / (1.f + expf(-g_gate[t * 3 + 0]));
    float* psum_out = g_psum + ((size_t)g * T + t) * 128;
    float* out = g_att + ((size_t)t * HQ + g * HG) * D;
    int d0 = m16 << 2;

    if (nc == 0) {
        *(float4*)(out + h * D + d0) = make_float4(0.f, 0.f, 0.f, 0.f);
        if (tid < 128) psum_out[tid] = 0.f;
        return;
    }
    for (int i = tid; i < nc * D; i += 256) {
        int c = i >> 6, d = i & 63;
        sbuf[c][d] = g_ck[((size_t)g * C_NUM + c) * D + d];
    }
    __syncthreads();

    float sv_[8];
    float mx = -INFINITY;
    const float* qh = sq + h * D;
#pragma unroll
    for (int r = 0; r < 8; r++) {
        int c = r * 16 + m16;
        float acc = -INFINITY;
        if (c < nc) {
            acc = 0.f;
#pragma unroll 8
            for (int d = 0; d < D; d++) acc += qh[d] * sbuf[c][d];
            acc *= SCALE;
        }
        sv_[r] = acc;
        mx = fmaxf(mx, acc);
    }
#pragma unroll
    for (int off = 8; off; off >>= 1)
        mx = fmaxf(mx, __shfl_xor_sync(0xffffffffu, mx, off, 16));
    float l = 0.f;
#pragma unroll
    for (int r = 0; r < 8; r++) { sv_[r] = __expf(sv_[r] - mx); l += sv_[r]; }
#pragma unroll
    for (int off = 8; off; off >>= 1)
        l += __shfl_xor_sync(0xffffffffu, l, off, 16);
    float invl = 1.f / l;
#pragma unroll
    for (int r = 0; r < 8; r++) sp[h][r * 16 + m16] = sv_[r] * invl;
    __syncthreads();

    if (tid < 128) {
        float s = 0.f;
        if (tid < nc) {
#pragma unroll
            for (int hh = 0; hh < HG; hh++) s += sp[hh][tid];
        }
        psum_out[tid] = s;
    }
    for (int i = tid; i < nc * D; i += 256) {
        int c = i >> 6, d = i & 63;
        sbuf[c][d] = g_cv[((size_t)g * C_NUM + c) * D + d];
    }
    __syncthreads();

    float a0 = 0, a1 = 0, a2 = 0, a3 = 0;
    for (int c = 0; c < nc; c++) {
        float p = sp[h][c];
        a0 += p * sbuf[c][d0 + 0];
        a1 += p * sbuf[c][d0 + 1];
        a2 += p * sbuf[c][d0 + 2];
        a3 += p * sbuf[c][d0 + 3];
    }
    out[h * D + d0 + 0] = gate0 * a0;
    out[h * D + d0 + 1] = gate0 * a1;
    out[h * D + d0 + 2] = gate0 * a2;
    out[h * D + d0 + 3] = gate0 * a3;
}

// ------------------------- block score + stable top-k ------------------------
__global__ void select_kernel() {
    int t = blockIdx.x, g = blockIdx.y;
    int b = threadIdx.x;
    const float* ps = g_psum + ((size_t)g * T + t) * 128;
    float sc = 0.f;
    int clo = 4 * b - 1; if (clo < 0) clo = 0;
    int chi = 4 * b + 3; if (chi > C_NUM - 1) chi = C_NUM - 1;
    for (int c = clo; c <= chi; c++) sc += ps[c];
    int qb = t >> 6;
    bool causal = (b <= qb);
    bool forced = (b < 1) || ((qb - b < 2) && causal);
    float val = causal ? (forced ? INFINITY : sc) : -INFINITY;
    unsigned selbits = 0;
    for (int it = 0; it < TOPK; it++) {
        float rv = val; int ri = b;
#pragma unroll
        for (int off = 16; off; off >>= 1) {
            float ov = __shfl_xor_sync(0xffffffffu, rv, off);
            int oi = __shfl_xor_sync(0xffffffffu, ri, off);
            if (ov > rv || (ov == rv && oi < ri)) { rv = ov; ri = oi; }
        }
        if (rv == -INFINITY) break;
        selbits |= (1u << ri);
        if (b == ri) val = -INFINITY;
    }
    if (b == 0) g_sel[(size_t)g * T + t] = selbits;
}

// ------------------------- MMA flash attention (sparse + sliding) ------------
__global__ __launch_bounds__(256) void attn_mma_kernel() {
    int t = blockIdx.x, g = blockIdx.y;
    int tid = threadIdx.x;
    int warp = tid >> 5, lane = tid & 31;
    int g8 = lane >> 2, tig = lane & 3;
    int mode = warp >> 2, w4 = warp & 3;

    __shared__ float sm_m[8][16];
    __shared__ float sm_l[8][16];
    __shared__ float sacc[8][16][64];

    int qb = t >> 6;
    int lo = t - WINDOW; if (lo < 0) lo = 0;
    unsigned mask;
    if (mode == 0) mask = g_sel[(size_t)g * T + t];
    else mask = ((2u << qb) - 1) & ~((1u << (lo >> 6)) - 1);

    // q fragments hi/lo, 4 k-chunks of 16 dims
    unsigned aqh[4][4], aql[4][4];
    {
        const float* qbase = g_q + ((size_t)t * HQ + g * HG) * D;
#pragma unroll
        for (int c = 0; c < 4; c++) {
            int d0 = c * 16 + 2 * tig;
            float2 v00 = *(const float2*)(qbase + g8 * D + d0);
            float2 v10 = *(const float2*)(qbase + (g8 + 8) * D + d0);
            float2 v01 = *(const float2*)(qbase + g8 * D + d0 + 8);
            float2 v11 = *(const float2*)(qbase + (g8 + 8) * D + d0 + 8);
            split2(v00.x, v00.y, aqh[c][0], aql[c][0]);
            split2(v10.x, v10.y, aqh[c][1], aql[c][1]);
            split2(v01.x, v01.y, aqh[c][2], aql[c][2]);
            split2(v11.x, v11.y, aqh[c][3], aql[c][3]);
        }
    }

    float m0 = -INFINITY, m1 = -INFINITY, l0 = 0.f, l1 = 0.f;
    float acc[8][4];
#pragma unroll
    for (int j = 0; j < 8; j++)
#pragma unroll
        for (int r = 0; r < 4; r++) acc[j][r] = 0.f;

    unsigned rem = mask;
    int bidx = 0;
    while (rem) {
        int b = __ffs(rem) - 1;
        rem &= rem - 1;
        if ((bidx++ & 3) != w4) continue;
        int sbase = b << 6;
        int smax = t - sbase; if (smax > 63) smax = 63;
        int smin = 0;
        if (mode == 1) { smin = lo - sbase; if (smin < 0) smin = 0; }

        // ----- QK: S[16 x 64] (permuted-fragment K, LDG.128) -----
        float S[8][4];
#pragma unroll
        for (int j = 0; j < 8; j++)
#pragma unroll
            for (int r = 0; r < 4; r++) S[j][r] = 0.f;

#pragma unroll
        for (int j = 0; j < 8; j++) {
            size_t rowoff = ((size_t)(sbase + 8 * j + g8) * G + g) * D;
            const uint4* ph = (const uint4*)(g_kh + rowoff) + tig * 2;
            const uint4* pl = (const uint4*)(g_kl + rowoff) + tig * 2;
            uint4 H0 = ph[0], H1 = ph[1];
            uint4 L0 = pl[0], L1 = pl[1];
            unsigned bh[4][2] = {{H0.x, H0.y}, {H0.z, H0.w},
                                 {H1.x, H1.y}, {H1.z, H1.w}};
            unsigned bl[4][2] = {{L0.x, L0.y}, {L0.z, L0.w},
                                 {L1.x, L1.y}, {L1.z, L1.w}};
#pragma unroll
            for (int c = 0; c < 4; c++) {
                MMA_BF16(S[j], aqh[c], bh[c]);
                MMA_BF16(S[j], aql[c], bh[c]);
                MMA_BF16(S[j], aqh[c], bl[c]);
            }
        }
        // mask + scale + per-block row max
        float bmax0 = -INFINITY, bmax1 = -INFINITY;
        int soff = 2 * tig;
#pragma unroll
        for (int j = 0; j < 8; j++) {
            int s0i = 8 * j + soff, s1i = s0i + 1;
            bool v0 = (s0i >= smin) && (s0i <= smax);
            bool v1 = (s1i >= smin) && (s1i <= smax);
            S[j][0] = v0 ? S[j][0] * SCALE : -INFINITY;
            S[j][1] = v1 ? S[j][1] * SCALE : -INFINITY;
            S[j][2] = v0 ? S[j][2] * SCALE : -INFINITY;
            S[j][3] = v1 ? S[j][3] * SCALE : -INFINITY;
            bmax0 = fmaxf(bmax0, fmaxf(S[j][0], S[j][1]));
            bmax1 = fmaxf(bmax1, fmaxf(S[j][2], S[j][3]));
        }
        bmax0 = fmaxf(bmax0, __shfl_xor_sync(0xffffffffu, bmax0, 1));
        bmax0 = fmaxf(bmax0, __shfl_xor_sync(0xffffffffu, bmax0, 2));
        bmax1 = fmaxf(bmax1, __shfl_xor_sync(0xffffffffu, bmax1, 1));
        bmax1 = fmaxf(bmax1, __shfl_xor_sync(0xffffffffu, bmax1, 2));
        float mn0 = fmaxf(m0, bmax0), mn1 = fmaxf(m1, bmax1);
        float cor0 = __expf(m0 - mn0), cor1 = __expf(m1 - mn1);
        m0 = mn0; m1 = mn1;

        unsigned ph0[8], ph1[8], pl0[8], pl1[8];
        float ps0 = 0.f, ps1 = 0.f;
#pragma unroll
        for (int j = 0; j < 8; j++) {
            float p0 = __expf(S[j][0] - mn0);
            float p1 = __expf(S[j][1] - mn0);
            float p2 = __expf(S[j][2] - mn1);
            float p3 = __expf(S[j][3] - mn1);
            ps0 += p0 + p1;
            ps1 += p2 + p3;
            split2(p0, p1, ph0[j], pl0[j]);
            split2(p2, p3, ph1[j], pl1[j]);
        }
        ps0 += __shfl_xor_sync(0xffffffffu, ps0, 1);
        ps0 += __shfl_xor_sync(0xffffffffu, ps0, 2);
        ps1 += __shfl_xor_sync(0xffffffffu, ps1, 1);
        ps1 += __shfl_xor_sync(0xffffffffu, ps1, 2);
        l0 = l0 * cor0 + ps0;
        l1 = l1 * cor1 + ps1;
#pragma unroll
        for (int j = 0; j < 8; j++) {
            acc[j][0] *= cor0; acc[j][1] *= cor0;
            acc[j][2] *= cor1; acc[j][3] *= cor1;
        }

        // ----- PV: acc += P @ V (permuted-fragment V^T, LDG.128) -----
#pragma unroll
        for (int jd = 0; jd < 8; jd++) {
            size_t rowoff = ((size_t)(g * D + g8 + 8 * jd)) * T + sbase;
            const uint4* pvh = (const uint4*)(g_vth + rowoff) + tig * 2;
            const uint4* pvl = (const uint4*)(g_vtl + rowoff) + tig * 2;
            uint4 H0 = pvh[0], H1 = pvh[1];
            uint4 L0 = pvl[0], L1 = pvl[1];
            unsigned bh[4][2] = {{H0.x, H0.y}, {H0.z, H0.w},
                                 {H1.x, H1.y}, {H1.z, H1.w}};
            unsigned bl[4][2] = {{L0.x, L0.y}, {L0.z, L0.w},
                                 {L1.x, L1.y}, {L1.z, L1.w}};
#pragma unroll
            for (int kc = 0; kc < 4; kc++) {
                unsigned ah[4] = {ph0[2 * kc], ph1[2 * kc],
                                  ph0[2 * kc + 1], ph1[2 * kc + 1]};
                unsigned al_[4] = {pl0[2 * kc], pl1[2 * kc],
                                   pl0[2 * kc + 1], pl1[2 * kc + 1]};
                MMA_BF16(acc[jd], ah, bh[kc]);
                MMA_BF16(acc[jd], al_, bh[kc]);
                MMA_BF16(acc[jd], ah, bl[kc]);
            }
        }
    }

    // per-warp state to smem
    if (tig == 0) {
        sm_m[warp][g8] = m0; sm_m[warp][g8 + 8] = m1;
        sm_l[warp][g8] = l0; sm_l[warp][g8 + 8] = l1;
    }
#pragma unroll
    for (int j = 0; j < 8; j++) {
        sacc[warp][g8][8 * j + 2 * tig] = acc[j][0];
        sacc[warp][g8][8 * j + 2 * tig + 1] = acc[j][1];
        sacc[warp][g8 + 8][8 * j + 2 * tig] = acc[j][2];
        sacc[warp][g8 + 8][8 * j + 2 * tig + 1] = acc[j][3];
    }
    __syncthreads();

    // merge the 4 partials of each branch; combine with gates
    int row = tid >> 4, col = (tid & 15) << 2;
    float M1 = sm_m[0][row], M2 = sm_m[4][row];
#pragma unroll
    for (int w = 1; w < 4; w++) {
        M1 = fmaxf(M1, sm_m[w][row]);
        M2 = fmaxf(M2, sm_m[4 + w][row]);
    }
    float L1 = 0.f, L2 = 0.f;
    float o1[4] = {0, 0, 0, 0}, o2[4] = {0, 0, 0, 0};
#pragma unroll
    for (int w = 0; w < 4; w++) {
        float f1 = __expf(sm_m[w][row] - M1);
        float f2 = __expf(sm_m[4 + w][row] - M2);
        L1 += f1 * sm_l[w][row];
        L2 += f2 * sm_l[4 + w][row];
        const float* a1 = &sacc[w][row][col];
        const float* a2 = &sacc[4 + w][row][col];
#pragma unroll
        for (int e = 0; e < 4; e++) {
            o1[e] += f1 * a1[e];
            o2[e] += f2 * a2[e];
        }
    }
    float gg1 = 1.f / (1.f + expf(-g_gate[t * 3 + 1]));
    float gg2 = 1.f / (1.f + expf(-g_gate[t * 3 + 2]));
    float w1 = gg1 / L1, w2 = gg2 / L2;
    float* op = g_att + ((size_t)t * HQ + g * HG + row) * D + col;
    float4 cur = *(float4*)op;
    cur.x += w1 * o1[0] + w2 * o2[0];
    cur.y += w1 * o1[1] + w2 * o2[1];
    cur.z += w1 * o1[2] + w2 * o2[2];
    cur.w += w1 * o1[3] + w2 * o2[3];
    *(float4*)op = cur;
}

// ------------------------- launch --------------------------------------------
extern "C" void kernel_launch(void* const* d_in, const int* in_sizes, int n_in,
                              void* d_out, int out_size) {
    const float* x   = (const float*)d_in[0];
    const float* Wq  = (const float*)d_in[1];
    const float* Wk  = (const float*)d_in[2];
    const float* Wv  = (const float*)d_in[3];
    const float* Wo  = (const float*)d_in[4];
    const float* Wg  = (const float*)d_in[5];
    const float* Wck = (const float*)d_in[6];
    const float* Wcv = (const float*)d_in[7];
    float* out = (float*)d_out;

    float *pq, *pk, *patt;
    cudaGetSymbolAddress((void**)&pq, g_q);
    cudaGetSymbolAddress((void**)&pk, g_k);
    cudaGetSymbolAddress((void**)&patt, g_att);
    __nv_bfloat16 *xh, *xl, *wqh, *wql, *wkh, *wkl, *wvh, *wvl, *woh, *wol,
        *ath, *atl;
    cudaGetSymbolAddress((void**)&xh, g_xh);
    cudaGetSymbolAddress((void**)&xl, g_xl);
    cudaGetSymbolAddress((void**)&wqh, g_wqh);
    cudaGetSymbolAddress((void**)&wql, g_wql);
    cudaGetSymbolAddress((void**)&wkh, g_wkh);
    cudaGetSymbolAddress((void**)&wkl, g_wkl);
    cudaGetSymbolAddress((void**)&wvh, g_wvh);
    cudaGetSymbolAddress((void**)&wvl, g_wvl);
    cudaGetSymbolAddress((void**)&woh, g_woh);
    cudaGetSymbolAddress((void**)&wol, g_wol);
    cudaGetSymbolAddress((void**)&ath, g_ath);
    cudaGetSymbolAddress((void**)&atl, g_atl);

    const int NELT = T * HID;
    const int NKV = G * D * HID;
    split_kernel<<<NELT / 1024, 256>>>(x, xh, xl, NELT);
    split_kernel<<<NELT / 1024, 256>>>(Wq, wqh, wql, NELT);
    split_kernel<<<NKV / 1024, 256>>>(Wk, wkh, wkl, NKV);
    split_kernel<<<NKV / 1024, 256>>>(Wv, wvh, wvl, NKV);
    split_kernel<<<NELT / 1024, 256>>>(Wo, woh, wol, NELT);
    rope_table_kernel<<<T, 32>>>();

    gemm_qkv<<<dim3(18, T / 128), 256>>>();
    gate_kernel<<<T, 96>>>(x, Wg);
    rope_apply_kernel<<<T, 256>>>(pq, HQ);
    rope_apply_kernel<<<T, 64>>>(pk, G);
    kvsplit_kernel<<<(T * G * D) / 256, 256>>>();
    compress_kernel<<<dim3(C_NUM, G, 2), 256>>>(Wck, Wcv);
    comp_attn_kernel<<<dim3(T, G), 256>>>();
    select_kernel<<<dim3(T, G), 32>>>();
    attn_mma_kernel<<<dim3(T, G), 256>>>();

    split_kernel<<<NELT / 1024, 256>>>(patt, ath, atl, NELT);
    gemm_bf16x3<<<dim3(HID / 128, T / 128), 256>>>(ath, atl, woh, wol, out,
                                                   T, HID, HID);
}